// round 1
// baseline (speedup 1.0000x reference)
#include <cuda_runtime.h>
#include <cstdint>

#define TOKENS 8192
#define HIDDEN 1024
#define INTER  2816
#define NEXP   8
#define NSLOTS (2*TOKENS)
#define MAX_TILES 160

#define BM 128
#define BN 128
#define BK 32

// ---------------- scratch (device globals; no allocation allowed) ----------------
__device__ int   g_cnt[NEXP];
__device__ int   g_cur[NEXP];
__device__ int   g_off[NEXP + 1];
__device__ int   g_e0[TOKENS];
__device__ int   g_e1[TOKENS];
__device__ float g_w0[TOKENS];
__device__ float g_w1[TOKENS];
__device__ int   g_row_token[NSLOTS];
__device__ float g_row_w[NSLOTS];
__device__ int   g_tile_e[MAX_TILES];
__device__ int   g_tile_m0[MAX_TILES];
__device__ int   g_tile_rows[MAX_TILES];
__device__ int   g_ntiles;
__device__ float g_act[(size_t)NSLOTS * INTER];   // 176 MB intermediate

// ---------------- small helpers ----------------
__device__ __forceinline__ uint32_t smem_u32(const void* p) {
    uint32_t a;
    asm("{ .reg .u64 t; cvta.to.shared.u64 t, %1; cvt.u32.u64 %0, t; }" : "=r"(a) : "l"(p));
    return a;
}

__device__ __forceinline__ void cp16(uint32_t dst, const void* src, int src_sz) {
    asm volatile("cp.async.cg.shared.global [%0], [%1], 16, %2;\n"
                 :: "r"(dst), "l"(src), "r"(src_sz) : "memory");
}
__device__ __forceinline__ void cp_commit() {
    asm volatile("cp.async.commit_group;\n" ::: "memory");
}
__device__ __forceinline__ void cp_wait1() {
    asm volatile("cp.async.wait_group 1;\n" ::: "memory");
}

__device__ __forceinline__ uint32_t f2tf32(float f) {
    uint32_t r;
    asm("cvt.rna.tf32.f32 %0, %1;" : "=r"(r) : "f"(f));
    return r;
}

__device__ __forceinline__ void mma_tf32(float* c, const uint32_t* a, const uint32_t* b) {
    asm volatile(
        "mma.sync.aligned.m16n8k8.row.col.f32.tf32.tf32.f32 "
        "{%0,%1,%2,%3},{%4,%5,%6,%7},{%8,%9},{%0,%1,%2,%3};"
        : "+f"(c[0]), "+f"(c[1]), "+f"(c[2]), "+f"(c[3])
        : "r"(a[0]), "r"(a[1]), "r"(a[2]), "r"(a[3]), "r"(b[0]), "r"(b[1]));
}

// XOR swizzle inside a [rows][32]-float tile: conflict-free frag loads + 16B cp.async stores
__device__ __forceinline__ int swz(int row, int col) {
    return row * 32 + ((col & 3) | ((((col >> 2) ^ row) & 7) << 2));
}

// ---------------- K0: zero expert counters ----------------
__global__ void k_zero() {
    if (threadIdx.x < NEXP) g_cnt[threadIdx.x] = 0;
}

// ---------------- K1: routing (logits -> top2 -> softmax) ----------------
__global__ void k_route(const float* __restrict__ x, const float* __restrict__ wg) {
    __shared__ float s_wg[NEXP * HIDDEN];
    int tid = threadIdx.x;
    for (int i = tid * 4; i < NEXP * HIDDEN; i += blockDim.x * 4)
        *(float4*)&s_wg[i] = *(const float4*)&wg[i];
    __syncthreads();

    int warp = tid >> 5, lane = tid & 31;
    int t = blockIdx.x * 8 + warp;

    float p[NEXP];
#pragma unroll
    for (int e = 0; e < NEXP; e++) p[e] = 0.f;

    const float* xr = x + (size_t)t * HIDDEN;
    for (int k = lane; k < HIDDEN; k += 32) {
        float xv = xr[k];
#pragma unroll
        for (int e = 0; e < NEXP; e++) p[e] += xv * s_wg[e * HIDDEN + k];
    }
#pragma unroll
    for (int e = 0; e < NEXP; e++) {
#pragma unroll
        for (int o = 16; o; o >>= 1) p[e] += __shfl_xor_sync(0xffffffffu, p[e], o);
    }
    if (lane == 0) {
        int e0 = 0;
#pragma unroll
        for (int e = 1; e < NEXP; e++) if (p[e] > p[e0]) e0 = e;
        int e1 = -1;
        float v1 = -1e30f;
#pragma unroll
        for (int e = 0; e < NEXP; e++) {
            if (e == e0) continue;
            if (e1 < 0 || p[e] > v1) { e1 = e; v1 = p[e]; }
        }
        float v0 = p[e0];
        float a = 1.0f;                 // exp(v0 - v0)
        float b = __expf(v1 - v0);
        float inv = 1.f / (a + b);
        g_e0[t] = e0; g_e1[t] = e1;
        g_w0[t] = a * inv; g_w1[t] = b * inv;
        atomicAdd(&g_cnt[e0], 1);
        atomicAdd(&g_cnt[e1], 1);
    }
}

// ---------------- K2: offsets + tile plan ----------------
__global__ void k_plan() {
    if (threadIdx.x == 0) {
        int off = 0, nt = 0;
        for (int e = 0; e < NEXP; e++) {
            g_off[e] = off;
            int c = g_cnt[e];
            int m0 = 0;
            while (m0 < c) {
                g_tile_e[nt] = e;
                g_tile_m0[nt] = off + m0;
                g_tile_rows[nt] = min(BM, c - m0);
                m0 += BM; nt++;
            }
            off += c;
            g_cur[e] = 0;
        }
        g_off[NEXP] = off;
        g_ntiles = nt;
    }
}

// ---------------- K3: scatter tokens into per-expert row lists ----------------
__global__ void k_scatter() {
    int t = blockIdx.x * blockDim.x + threadIdx.x;
    if (t >= TOKENS) return;
    int e0 = g_e0[t], e1 = g_e1[t];
    int p0 = atomicAdd(&g_cur[e0], 1);
    int i0 = g_off[e0] + p0;
    g_row_token[i0] = t; g_row_w[i0] = g_w0[t];
    int p1 = atomicAdd(&g_cur[e1], 1);
    int i1 = g_off[e1] + p1;
    g_row_token[i1] = t; g_row_w[i1] = g_w1[t];
}

// ---------------- K4: fused gate+up GEMM + SwiGLU -> g_act ----------------
// block: [128 tokens] x [128 of INTER], two B matrices (gate, up)
// 8 warps as 2(m) x 4(n), warp tile 64x32, BK=32, cp.async double buffer
__global__ void __launch_bounds__(256)
k_gateup(const float* __restrict__ x,
         const float* __restrict__ wgp,
         const float* __restrict__ wup) {
    int bt = blockIdx.y;
    if (bt >= g_ntiles) return;
    int e = g_tile_e[bt];
    int m0 = g_tile_m0[bt];
    int rows = g_tile_rows[bt];
    int n0 = blockIdx.x * BN;

    extern __shared__ float dsm[];
    // layout per buffer: A[4096] | G[4096] | U[4096]
    const int STAGE = 3 * BM * BK;     // 12288 floats
    uint32_t sbase = smem_u32(dsm);

    int tid = threadIdx.x;
    int warp = tid >> 5, lane = tid & 31;
    int wm = warp & 1, wn = warp >> 1;

    const float* wgp_e = wgp + (size_t)e * INTER * HIDDEN;
    const float* wup_e = wup + (size_t)e * INTER * HIDDEN;

    // per-thread load descriptors: 4 chunks per tile (chunk = 16B)
    const float* a_src[4]; int a_sz[4];
    const float* bg_src[4];
    const float* bu_src[4];
    int c_r[4], c_c4[4];
#pragma unroll
    for (int i = 0; i < 4; i++) {
        int c = tid + 256 * i;
        int r = c >> 3, c4 = c & 7;
        c_r[i] = r; c_c4[i] = c4;
        bool v = r < rows;
        int tok = v ? g_row_token[m0 + r] : 0;
        a_src[i] = x + (size_t)tok * HIDDEN + c4 * 4;
        a_sz[i] = v ? 16 : 0;
        bg_src[i] = wgp_e + (size_t)(n0 + r) * HIDDEN + c4 * 4;
        bu_src[i] = wup_e + (size_t)(n0 + r) * HIDDEN + c4 * 4;
    }

    float accG[4][4][4], accU[4][4][4];
#pragma unroll
    for (int a = 0; a < 4; a++)
#pragma unroll
        for (int b = 0; b < 4; b++)
#pragma unroll
            for (int q = 0; q < 4; q++) { accG[a][b][q] = 0.f; accU[a][b][q] = 0.f; }

    const int KT = HIDDEN / BK;   // 32

    // stage loader
    auto load_stage = [&](int kt, int buf) {
        uint32_t base = sbase + (uint32_t)(buf * STAGE) * 4u;
#pragma unroll
        for (int i = 0; i < 4; i++) {
            int r = c_r[i], c4 = c_c4[i];
            uint32_t soff = (uint32_t)(r * 32 + ((c4 ^ (r & 7)) << 2)) * 4u;
            cp16(base + soff,                     a_src[i]  + kt * BK, a_sz[i]);
            cp16(base + 4096u * 4u + soff,        bg_src[i] + kt * BK, 16);
            cp16(base + 8192u * 4u + soff,        bu_src[i] + kt * BK, 16);
        }
    };

    load_stage(0, 0);
    cp_commit();

    for (int kt = 0; kt < KT; kt++) {
        int buf = kt & 1;
        if (kt + 1 < KT) load_stage(kt + 1, buf ^ 1);
        cp_commit();
        cp_wait1();
        __syncthreads();

        const float* sA = dsm + buf * STAGE;
        const float* sG = sA + 4096;
        const float* sU = sG + 4096;

#pragma unroll
        for (int s = 0; s < 4; s++) {
            uint32_t af[4][4];
#pragma unroll
            for (int mi = 0; mi < 4; mi++) {
                int row = wm * 64 + mi * 16 + (lane >> 2);
                int col = s * 8 + (lane & 3);
                af[mi][0] = f2tf32(sA[swz(row,     col)]);
                af[mi][1] = f2tf32(sA[swz(row + 8, col)]);
                af[mi][2] = f2tf32(sA[swz(row,     col + 4)]);
                af[mi][3] = f2tf32(sA[swz(row + 8, col + 4)]);
            }
            uint32_t bg[4][2], bu[4][2];
#pragma unroll
            for (int ni = 0; ni < 4; ni++) {
                int nr = wn * 32 + ni * 8 + (lane >> 2);
                int col = s * 8 + (lane & 3);
                bg[ni][0] = f2tf32(sG[swz(nr, col)]);
                bg[ni][1] = f2tf32(sG[swz(nr, col + 4)]);
                bu[ni][0] = f2tf32(sU[swz(nr, col)]);
                bu[ni][1] = f2tf32(sU[swz(nr, col + 4)]);
            }
#pragma unroll
            for (int mi = 0; mi < 4; mi++)
#pragma unroll
                for (int ni = 0; ni < 4; ni++) {
                    mma_tf32(accG[mi][ni], af[mi], bg[ni]);
                    mma_tf32(accU[mi][ni], af[mi], bu[ni]);
                }
        }
        __syncthreads();
    }

    // epilogue: act = silu(g) * u
#pragma unroll
    for (int mi = 0; mi < 4; mi++) {
        int r_lo = wm * 64 + mi * 16 + (lane >> 2);
#pragma unroll
        for (int half = 0; half < 2; half++) {
            int row = r_lo + half * 8;
            if (row >= rows) continue;
            float* actrow = g_act + (size_t)(m0 + row) * INTER;
#pragma unroll
            for (int ni = 0; ni < 4; ni++) {
                int coln = n0 + wn * 32 + ni * 8 + (lane & 3) * 2;
                float g0 = accG[mi][ni][half * 2 + 0];
                float g1 = accG[mi][ni][half * 2 + 1];
                float u0 = accU[mi][ni][half * 2 + 0];
                float u1 = accU[mi][ni][half * 2 + 1];
                float s0 = g0 / (1.f + __expf(-g0)) * u0;
                float s1 = g1 / (1.f + __expf(-g1)) * u1;
                *(float2*)&actrow[coln] = make_float2(s0, s1);
            }
        }
    }
}

// ---------------- K5: down-proj GEMM + weighted scatter-add ----------------
__global__ void __launch_bounds__(256)
k_down(const float* __restrict__ wdp, float* __restrict__ out) {
    int bt = blockIdx.y;
    if (bt >= g_ntiles) return;
    int e = g_tile_e[bt];
    int m0 = g_tile_m0[bt];
    int rows = g_tile_rows[bt];
    int n0 = blockIdx.x * BN;

    extern __shared__ float dsm[];
    const int STAGE = 2 * BM * BK;   // 8192 floats: A[4096] | B[4096]
    uint32_t sbase = smem_u32(dsm);

    int tid = threadIdx.x;
    int warp = tid >> 5, lane = tid & 31;
    int wm = warp & 1, wn = warp >> 1;

    const float* wd_e = wdp + (size_t)e * HIDDEN * INTER;

    const float* a_src[4]; int a_sz[4];
    const float* b_src[4];
    int c_r[4], c_c4[4];
#pragma unroll
    for (int i = 0; i < 4; i++) {
        int c = tid + 256 * i;
        int r = c >> 3, c4 = c & 7;
        c_r[i] = r; c_c4[i] = c4;
        bool v = r < rows;
        a_src[i] = v ? (g_act + (size_t)(m0 + r) * INTER + c4 * 4) : g_act;
        a_sz[i] = v ? 16 : 0;
        b_src[i] = wd_e + (size_t)(n0 + r) * INTER + c4 * 4;
    }

    float acc[4][4][4];
#pragma unroll
    for (int a = 0; a < 4; a++)
#pragma unroll
        for (int b = 0; b < 4; b++)
#pragma unroll
            for (int q = 0; q < 4; q++) acc[a][b][q] = 0.f;

    const int KT = INTER / BK;   // 88

    auto load_stage = [&](int kt, int buf) {
        uint32_t base = sbase + (uint32_t)(buf * STAGE) * 4u;
#pragma unroll
        for (int i = 0; i < 4; i++) {
            int r = c_r[i], c4 = c_c4[i];
            uint32_t soff = (uint32_t)(r * 32 + ((c4 ^ (r & 7)) << 2)) * 4u;
            cp16(base + soff,              a_src[i] + kt * BK, a_sz[i]);
            cp16(base + 4096u * 4u + soff, b_src[i] + kt * BK, 16);
        }
    };

    load_stage(0, 0);
    cp_commit();

    for (int kt = 0; kt < KT; kt++) {
        int buf = kt & 1;
        if (kt + 1 < KT) load_stage(kt + 1, buf ^ 1);
        cp_commit();
        cp_wait1();
        __syncthreads();

        const float* sA = dsm + buf * STAGE;
        const float* sB = sA + 4096;

#pragma unroll
        for (int s = 0; s < 4; s++) {
            uint32_t af[4][4];
#pragma unroll
            for (int mi = 0; mi < 4; mi++) {
                int row = wm * 64 + mi * 16 + (lane >> 2);
                int col = s * 8 + (lane & 3);
                af[mi][0] = f2tf32(sA[swz(row,     col)]);
                af[mi][1] = f2tf32(sA[swz(row + 8, col)]);
                af[mi][2] = f2tf32(sA[swz(row,     col + 4)]);
                af[mi][3] = f2tf32(sA[swz(row + 8, col + 4)]);
            }
            uint32_t bf[4][2];
#pragma unroll
            for (int ni = 0; ni < 4; ni++) {
                int nr = wn * 32 + ni * 8 + (lane >> 2);
                int col = s * 8 + (lane & 3);
                bf[ni][0] = f2tf32(sB[swz(nr, col)]);
                bf[ni][1] = f2tf32(sB[swz(nr, col + 4)]);
            }
#pragma unroll
            for (int mi = 0; mi < 4; mi++)
#pragma unroll
                for (int ni = 0; ni < 4; ni++)
                    mma_tf32(acc[mi][ni], af[mi], bf[ni]);
        }
        __syncthreads();
    }

    // epilogue: out[token] += w * acc (exactly 2 adds per element -> deterministic)
#pragma unroll
    for (int mi = 0; mi < 4; mi++) {
        int r_lo = wm * 64 + mi * 16 + (lane >> 2);
#pragma unroll
        for (int half = 0; half < 2; half++) {
            int row = r_lo + half * 8;
            if (row >= rows) continue;
            int tok = g_row_token[m0 + row];
            float w = g_row_w[m0 + row];
            float* orow = out + (size_t)tok * HIDDEN;
#pragma unroll
            for (int ni = 0; ni < 4; ni++) {
                int coln = n0 + wn * 32 + ni * 8 + (lane & 3) * 2;
                atomicAdd(&orow[coln],     w * acc[mi][ni][half * 2 + 0]);
                atomicAdd(&orow[coln + 1], w * acc[mi][ni][half * 2 + 1]);
            }
        }
    }
}

// ---------------- launch ----------------
extern "C" void kernel_launch(void* const* d_in, const int* in_sizes, int n_in,
                              void* d_out, int out_size) {
    const float* x   = (const float*)d_in[0];   // hidden_states [8192,1024]
    const float* wg  = (const float*)d_in[1];   // w_gate        [8,1024]
    const float* wgp = (const float*)d_in[2];   // w_gate_proj   [8,2816,1024]
    const float* wup = (const float*)d_in[3];   // w_up_proj     [8,2816,1024]
    const float* wdp = (const float*)d_in[4];   // w_down_proj   [8,1024,2816]
    float* out = (float*)d_out;

    cudaFuncSetAttribute(k_gateup, cudaFuncAttributeMaxDynamicSharedMemorySize, 98304);
    cudaFuncSetAttribute(k_down,   cudaFuncAttributeMaxDynamicSharedMemorySize, 65536);

    k_zero<<<1, 32>>>();
    k_route<<<TOKENS / 8, 256>>>(x, wg);
    k_plan<<<1, 1>>>();
    k_scatter<<<TOKENS / 256, 256>>>();
    cudaMemsetAsync(d_out, 0, (size_t)TOKENS * HIDDEN * sizeof(float));
    k_gateup<<<dim3(INTER / BN, 136), 256, 98304>>>(x, wgp, wup);
    k_down<<<dim3(HIDDEN / BN, 136), 256, 65536>>>(wdp, out);
}

// round 3
// speedup vs baseline: 1.1229x; 1.1229x over previous
#include <cuda_runtime.h>
#include <cstdint>

#define TOKENS 8192
#define HIDDEN 1024
#define INTER  2816
#define NEXP   8
#define NSLOTS (2*TOKENS)
#define MAX_TILES 160
#define BM 128

// ---------------- device scratch ----------------
__device__ int   g_cnt[NEXP];
__device__ int   g_cur[NEXP];
__device__ int   g_off[NEXP + 1];
__device__ int   g_e0[TOKENS];
__device__ int   g_e1[TOKENS];
__device__ float g_w0[TOKENS];
__device__ float g_w1[TOKENS];
__device__ int   g_row_token[NSLOTS];
__device__ int   g_slot0[TOKENS];
__device__ int   g_slot1[TOKENS];
__device__ int   g_tile_e[MAX_TILES];
__device__ int   g_tile_m0[MAX_TILES];
__device__ int   g_tile_rows[MAX_TILES];
__device__ int   g_ntiles;

__device__ float g_xr  [(size_t)TOKENS * HIDDEN];        // rna-tf32 x
__device__ float g_wgpr[(size_t)NEXP * INTER * HIDDEN];  // rna-tf32 gate proj
__device__ float g_wupr[(size_t)NEXP * INTER * HIDDEN];  // rna-tf32 up proj
__device__ float g_wdpr[(size_t)NEXP * HIDDEN * INTER];  // rna-tf32 down proj
__device__ float g_act [(size_t)NSLOTS * INTER];         // swiglu out (rna-tf32)
__device__ float g_dout[(size_t)NSLOTS * HIDDEN];        // unweighted expert rows

// ---------------- helpers ----------------
__device__ __forceinline__ uint32_t smem_u32(const void* p) {
    uint32_t a;
    asm("{ .reg .u64 t; cvta.to.shared.u64 t, %1; cvt.u32.u64 %0, t; }" : "=r"(a) : "l"(p));
    return a;
}
__device__ __forceinline__ void cp16(uint32_t dst, const void* src, int src_sz) {
    asm volatile("cp.async.cg.shared.global [%0], [%1], 16, %2;\n"
                 :: "r"(dst), "l"(src), "r"(src_sz) : "memory");
}
__device__ __forceinline__ void cp_commit() {
    asm volatile("cp.async.commit_group;\n" ::: "memory");
}
__device__ __forceinline__ void cp_wait2() {
    asm volatile("cp.async.wait_group 2;\n" ::: "memory");
}
__device__ __forceinline__ uint32_t f2tf32(float f) {
    uint32_t r;
    asm("cvt.rna.tf32.f32 %0, %1;" : "=r"(r) : "f"(f));
    return r;
}
__device__ __forceinline__ void mma_tf32(float* c, const uint32_t* a, const uint32_t* b) {
    asm volatile(
        "mma.sync.aligned.m16n8k8.row.col.f32.tf32.tf32.f32 "
        "{%0,%1,%2,%3},{%4,%5,%6,%7},{%8,%9},{%0,%1,%2,%3};"
        : "+f"(c[0]), "+f"(c[1]), "+f"(c[2]), "+f"(c[3])
        : "r"(a[0]), "r"(a[1]), "r"(a[2]), "r"(a[3]), "r"(b[0]), "r"(b[1]));
}
// word index inside a [rows][32-float] tile, XOR-swizzled (conflict-free)
__device__ __forceinline__ int swz(int row, int col) {
    return row * 32 + ((col & 3) | ((((col >> 2) ^ row) & 7) << 2));
}

// ---------------- routing ----------------
__global__ void k_zero() { if (threadIdx.x < NEXP) g_cnt[threadIdx.x] = 0; }

__global__ void k_route(const float* __restrict__ x, const float* __restrict__ wg) {
    __shared__ float s_wg[NEXP * HIDDEN];
    int tid = threadIdx.x;
    for (int i = tid * 4; i < NEXP * HIDDEN; i += blockDim.x * 4)
        *(float4*)&s_wg[i] = *(const float4*)&wg[i];
    __syncthreads();
    int warp = tid >> 5, lane = tid & 31;
    int t = blockIdx.x * 8 + warp;
    float p[NEXP];
#pragma unroll
    for (int e = 0; e < NEXP; e++) p[e] = 0.f;
    const float* xr = x + (size_t)t * HIDDEN;
    for (int k = lane; k < HIDDEN; k += 32) {
        float xv = xr[k];
#pragma unroll
        for (int e = 0; e < NEXP; e++) p[e] += xv * s_wg[e * HIDDEN + k];
    }
#pragma unroll
    for (int e = 0; e < NEXP; e++)
#pragma unroll
        for (int o = 16; o; o >>= 1) p[e] += __shfl_xor_sync(0xffffffffu, p[e], o);
    if (lane == 0) {
        int e0 = 0;
#pragma unroll
        for (int e = 1; e < NEXP; e++) if (p[e] > p[e0]) e0 = e;
        int e1 = -1; float v1 = -1e30f;
#pragma unroll
        for (int e = 0; e < NEXP; e++) {
            if (e == e0) continue;
            if (e1 < 0 || p[e] > v1) { e1 = e; v1 = p[e]; }
        }
        float b = __expf(v1 - p[e0]);
        float inv = 1.f / (1.f + b);
        g_e0[t] = e0; g_e1[t] = e1;
        g_w0[t] = inv; g_w1[t] = b * inv;
        atomicAdd(&g_cnt[e0], 1);
        atomicAdd(&g_cnt[e1], 1);
    }
}

__global__ void k_plan() {
    if (threadIdx.x == 0) {
        int off = 0, nt = 0;
        for (int e = 0; e < NEXP; e++) {
            g_off[e] = off;
            int c = g_cnt[e];
            int m0 = 0;
            while (m0 < c) {
                g_tile_e[nt] = e;
                g_tile_m0[nt] = off + m0;
                g_tile_rows[nt] = min(BM, c - m0);
                m0 += BM; nt++;
            }
            off += c;
            g_cur[e] = 0;
        }
        g_off[NEXP] = off;
        g_ntiles = nt;
    }
}

__global__ void k_scatter() {
    int t = blockIdx.x * blockDim.x + threadIdx.x;
    if (t >= TOKENS) return;
    int e0 = g_e0[t], e1 = g_e1[t];
    int i0 = g_off[e0] + atomicAdd(&g_cur[e0], 1);
    g_row_token[i0] = t; g_slot0[t] = i0;
    int i1 = g_off[e1] + atomicAdd(&g_cur[e1], 1);
    g_row_token[i1] = t; g_slot1[t] = i1;
}

// ---------------- rna-tf32 pre-rounding ----------------
__global__ void k_round(const float* __restrict__ src, int which, int n4) {
    int i = blockIdx.x * blockDim.x + threadIdx.x;
    if (i >= n4) return;
    float* dst = (which == 0) ? g_xr : (which == 1) ? g_wgpr : (which == 2) ? g_wupr : g_wdpr;
    float4 v = ((const float4*)src)[i];
    v.x = __uint_as_float(f2tf32(v.x));
    v.y = __uint_as_float(f2tf32(v.y));
    v.z = __uint_as_float(f2tf32(v.z));
    v.w = __uint_as_float(f2tf32(v.w));
    ((float4*)dst)[i] = v;
}

// ---------------- K4: gate+up GEMM + SwiGLU ----------------
// block 128(tok) x 128(inter), both gate and up; 8 warps as 2(m) x 4(n),
// warp tile 64x32 per matrix; BK=32; 3-stage cp.async ring; raw-uint tf32 MMA.
__global__ void __launch_bounds__(256, 1)
k_gateup() {
    int bt = blockIdx.y;
    if (bt >= g_ntiles) return;
    int e = g_tile_e[bt], m0 = g_tile_m0[bt], rows = g_tile_rows[bt];
    int n0 = blockIdx.x * 128;

    extern __shared__ float dsm[];
    // stage = A[4096] | G[4096] | U[4096] floats
    const int STAGE = 12288;
    uint32_t sbase = smem_u32(dsm);

    int tid = threadIdx.x, warp = tid >> 5, lane = tid & 31;
    int wm = warp & 1, wn = warp >> 1;

    const float* wg_e = g_wgpr + (size_t)e * INTER * HIDDEN;
    const float* wu_e = g_wupr + (size_t)e * INTER * HIDDEN;

    const float* a_src[4]; int a_sz[4];
    const float* bg_src[4]; const float* bu_src[4];
    uint32_t soff[4];
#pragma unroll
    for (int i = 0; i < 4; i++) {
        int c = tid + 256 * i;
        int r = c >> 3, c4 = c & 7;
        bool v = r < rows;
        int tok = v ? g_row_token[m0 + r] : 0;
        a_src[i] = g_xr + (size_t)tok * HIDDEN + c4 * 4;
        a_sz[i] = v ? 16 : 0;
        bg_src[i] = wg_e + (size_t)(n0 + r) * HIDDEN + c4 * 4;
        bu_src[i] = wu_e + (size_t)(n0 + r) * HIDDEN + c4 * 4;
        soff[i] = (uint32_t)(r * 32 + ((c4 ^ (r & 7)) << 2)) * 4u;
    }

    float accG[4][4][4], accU[4][4][4];
#pragma unroll
    for (int a = 0; a < 4; a++)
#pragma unroll
        for (int b = 0; b < 4; b++)
#pragma unroll
            for (int q = 0; q < 4; q++) { accG[a][b][q] = 0.f; accU[a][b][q] = 0.f; }

    auto load_stage = [&](int kt, int buf) {
        uint32_t base = sbase + (uint32_t)(buf * STAGE) * 4u;
#pragma unroll
        for (int i = 0; i < 4; i++) {
            cp16(base + soff[i],                a_src[i]  + kt * 32, a_sz[i]);
            cp16(base + 16384u + soff[i],       bg_src[i] + kt * 32, 16);
            cp16(base + 32768u + soff[i],       bu_src[i] + kt * 32, 16);
        }
    };

    load_stage(0, 0); cp_commit();
    load_stage(1, 1); cp_commit();
    load_stage(2, 2); cp_commit();

    const int KT = HIDDEN / 32;  // 32
    for (int kt = 0; kt < KT; kt++) {
        int buf = kt % 3;
        cp_wait2();
        __syncthreads();

        const uint32_t* sA = (const uint32_t*)(dsm + buf * STAGE);
        const uint32_t* sG = sA + 4096;
        const uint32_t* sU = sG + 4096;

#pragma unroll
        for (int s = 0; s < 4; s++) {
            uint32_t af[4][4];
#pragma unroll
            for (int mi = 0; mi < 4; mi++) {
                int row = wm * 64 + mi * 16 + (lane >> 2);
                int col = s * 8 + (lane & 3);
                af[mi][0] = sA[swz(row,     col)];
                af[mi][1] = sA[swz(row + 8, col)];
                af[mi][2] = sA[swz(row,     col + 4)];
                af[mi][3] = sA[swz(row + 8, col + 4)];
            }
            uint32_t bg[4][2], bu[4][2];
#pragma unroll
            for (int ni = 0; ni < 4; ni++) {
                int nr = wn * 32 + ni * 8 + (lane >> 2);
                int col = s * 8 + (lane & 3);
                bg[ni][0] = sG[swz(nr, col)];
                bg[ni][1] = sG[swz(nr, col + 4)];
                bu[ni][0] = sU[swz(nr, col)];
                bu[ni][1] = sU[swz(nr, col + 4)];
            }
#pragma unroll
            for (int mi = 0; mi < 4; mi++)
#pragma unroll
                for (int ni = 0; ni < 4; ni++) {
                    mma_tf32(accG[mi][ni], af[mi], bg[ni]);
                    mma_tf32(accU[mi][ni], af[mi], bu[ni]);
                }
        }
        __syncthreads();
        if (kt + 3 < KT) load_stage(kt + 3, buf);
        cp_commit();
    }

    // epilogue: act = rna_tf32(silu(g) * u)
#pragma unroll
    for (int mi = 0; mi < 4; mi++) {
        int r_lo = wm * 64 + mi * 16 + (lane >> 2);
#pragma unroll
        for (int half = 0; half < 2; half++) {
            int row = r_lo + half * 8;
            if (row >= rows) continue;
            float* arow = g_act + (size_t)(m0 + row) * INTER;
#pragma unroll
            for (int ni = 0; ni < 4; ni++) {
                int coln = n0 + wn * 32 + ni * 8 + (lane & 3) * 2;
                float g0 = accG[mi][ni][half * 2 + 0];
                float g1 = accG[mi][ni][half * 2 + 1];
                float u0 = accU[mi][ni][half * 2 + 0];
                float u1 = accU[mi][ni][half * 2 + 1];
                float s0 = g0 / (1.f + __expf(-g0)) * u0;
                float s1 = g1 / (1.f + __expf(-g1)) * u1;
                float2 o;
                o.x = __uint_as_float(f2tf32(s0));
                o.y = __uint_as_float(f2tf32(s1));
                *(float2*)&arow[coln] = o;
            }
        }
    }
}

// ---------------- K5: down GEMM -> unweighted rows ----------------
// block 128(slots) x 256(hidden); 8 warps as 2(m) x 4(n), warp tile 64x64.
__global__ void __launch_bounds__(256, 1)
k_down() {
    int bt = blockIdx.y;
    if (bt >= g_ntiles) return;
    int e = g_tile_e[bt], m0 = g_tile_m0[bt], rows = g_tile_rows[bt];
    int n0 = blockIdx.x * 256;

    extern __shared__ float dsm[];
    // stage = A[4096] | B[8192] floats
    const int STAGE = 12288;
    uint32_t sbase = smem_u32(dsm);

    int tid = threadIdx.x, warp = tid >> 5, lane = tid & 31;
    int wm = warp & 1, wn = warp >> 1;

    const float* wd_e = g_wdpr + (size_t)e * HIDDEN * INTER;

    const float* a_src[4]; int a_sz[4]; uint32_t a_off[4];
    const float* b_src[8]; uint32_t b_off[8];
#pragma unroll
    for (int i = 0; i < 4; i++) {
        int c = tid + 256 * i;
        int r = c >> 3, c4 = c & 7;
        bool v = r < rows;
        a_src[i] = g_act + (size_t)(m0 + (v ? r : 0)) * INTER + c4 * 4;
        a_sz[i] = v ? 16 : 0;
        a_off[i] = (uint32_t)(r * 32 + ((c4 ^ (r & 7)) << 2)) * 4u;
    }
#pragma unroll
    for (int i = 0; i < 8; i++) {
        int c = tid + 256 * i;
        int r = c >> 3, c4 = c & 7;
        b_src[i] = wd_e + (size_t)(n0 + r) * INTER + c4 * 4;
        b_off[i] = (uint32_t)(r * 32 + ((c4 ^ (r & 7)) << 2)) * 4u;
    }

    float acc[4][8][4];
#pragma unroll
    for (int a = 0; a < 4; a++)
#pragma unroll
        for (int b = 0; b < 8; b++)
#pragma unroll
            for (int q = 0; q < 4; q++) acc[a][b][q] = 0.f;

    auto load_stage = [&](int kt, int buf) {
        uint32_t base = sbase + (uint32_t)(buf * STAGE) * 4u;
#pragma unroll
        for (int i = 0; i < 4; i++)
            cp16(base + a_off[i], a_src[i] + kt * 32, a_sz[i]);
#pragma unroll
        for (int i = 0; i < 8; i++)
            cp16(base + 16384u + b_off[i], b_src[i] + kt * 32, 16);
    };

    load_stage(0, 0); cp_commit();
    load_stage(1, 1); cp_commit();
    load_stage(2, 2); cp_commit();

    const int KT = INTER / 32;  // 88
    for (int kt = 0; kt < KT; kt++) {
        int buf = kt % 3;
        cp_wait2();
        __syncthreads();

        const uint32_t* sA = (const uint32_t*)(dsm + buf * STAGE);
        const uint32_t* sB = sA + 4096;

#pragma unroll
        for (int s = 0; s < 4; s++) {
            uint32_t af[4][4];
#pragma unroll
            for (int mi = 0; mi < 4; mi++) {
                int row = wm * 64 + mi * 16 + (lane >> 2);
                int col = s * 8 + (lane & 3);
                af[mi][0] = sA[swz(row,     col)];
                af[mi][1] = sA[swz(row + 8, col)];
                af[mi][2] = sA[swz(row,     col + 4)];
                af[mi][3] = sA[swz(row + 8, col + 4)];
            }
            uint32_t bf[8][2];
#pragma unroll
            for (int ni = 0; ni < 8; ni++) {
                int nr = wn * 64 + ni * 8 + (lane >> 2);
                int col = s * 8 + (lane & 3);
                bf[ni][0] = sB[swz(nr, col)];
                bf[ni][1] = sB[swz(nr, col + 4)];
            }
#pragma unroll
            for (int mi = 0; mi < 4; mi++)
#pragma unroll
                for (int ni = 0; ni < 8; ni++)
                    mma_tf32(acc[mi][ni], af[mi], bf[ni]);
        }
        __syncthreads();
        if (kt + 3 < KT) load_stage(kt + 3, buf);
        cp_commit();
    }

    // epilogue: unweighted rows -> g_dout
#pragma unroll
    for (int mi = 0; mi < 4; mi++) {
        int r_lo = wm * 64 + mi * 16 + (lane >> 2);
#pragma unroll
        for (int half = 0; half < 2; half++) {
            int row = r_lo + half * 8;
            if (row >= rows) continue;
            float* orow = g_dout + (size_t)(m0 + row) * HIDDEN;
#pragma unroll
            for (int ni = 0; ni < 8; ni++) {
                int coln = n0 + wn * 64 + ni * 8 + (lane & 3) * 2;
                float2 o;
                o.x = acc[mi][ni][half * 2 + 0];
                o.y = acc[mi][ni][half * 2 + 1];
                *(float2*)&orow[coln] = o;
            }
        }
    }
}

// ---------------- combine ----------------
__global__ void k_combine(float* __restrict__ out) {
    int t = blockIdx.x, j = threadIdx.x;
    int s0 = g_slot0[t], s1 = g_slot1[t];
    float w0 = g_w0[t], w1 = g_w1[t];
    float4 a = ((const float4*)(g_dout + (size_t)s0 * HIDDEN))[j];
    float4 b = ((const float4*)(g_dout + (size_t)s1 * HIDDEN))[j];
    float4 o;
    o.x = w0 * a.x + w1 * b.x;
    o.y = w0 * a.y + w1 * b.y;
    o.z = w0 * a.z + w1 * b.z;
    o.w = w0 * a.w + w1 * b.w;
    ((float4*)(out + (size_t)t * HIDDEN))[j] = o;
}

// ---------------- launch ----------------
extern "C" void kernel_launch(void* const* d_in, const int* in_sizes, int n_in,
                              void* d_out, int out_size) {
    const float* x   = (const float*)d_in[0];
    const float* wg  = (const float*)d_in[1];
    const float* wgp = (const float*)d_in[2];
    const float* wup = (const float*)d_in[3];
    const float* wdp = (const float*)d_in[4];
    float* out = (float*)d_out;

    const int SMEM_DYN = 3 * 12288 * 4;  // 147456 B
    cudaFuncSetAttribute(k_gateup, cudaFuncAttributeMaxDynamicSharedMemorySize, SMEM_DYN);
    cudaFuncSetAttribute(k_down,   cudaFuncAttributeMaxDynamicSharedMemorySize, SMEM_DYN);

    k_zero<<<1, 32>>>();
    k_route<<<TOKENS / 8, 256>>>(x, wg);
    k_plan<<<1, 1>>>();
    k_scatter<<<TOKENS / 256, 256>>>();

    const int NX = TOKENS * HIDDEN / 4;
    const int NW = NEXP * INTER * HIDDEN / 4;
    k_round<<<(NX + 255) / 256, 256>>>(x,   0, NX);
    k_round<<<(NW + 255) / 256, 256>>>(wgp, 1, NW);
    k_round<<<(NW + 255) / 256, 256>>>(wup, 2, NW);
    k_round<<<(NW + 255) / 256, 256>>>(wdp, 3, NW);

    k_gateup<<<dim3(INTER / 128, 136), 256, SMEM_DYN>>>();
    k_down  <<<dim3(HIDDEN / 256, 136), 256, SMEM_DYN>>>();
    k_combine<<<TOKENS, 256>>>(out);
}

// round 4
// speedup vs baseline: 2.0197x; 1.7985x over previous
#include <cuda_runtime.h>
#include <cuda_fp16.h>
#include <cstdint>

#define TOKENS 8192
#define HIDDEN 1024
#define INTER  2816
#define NEXP   8
#define NSLOTS (2*TOKENS)
#define MAX_TILES 160
#define BM 128

// ---------------- device scratch ----------------
__device__ int   g_cnt[NEXP];
__device__ int   g_cur[NEXP];
__device__ int   g_off[NEXP + 1];
__device__ int   g_e0[TOKENS];
__device__ int   g_e1[TOKENS];
__device__ float g_w0[TOKENS];
__device__ float g_w1[TOKENS];
__device__ int   g_row_token[NSLOTS];
__device__ int   g_slot0[TOKENS];
__device__ int   g_slot1[TOKENS];
__device__ int   g_tile_e[MAX_TILES];
__device__ int   g_tile_m0[MAX_TILES];
__device__ int   g_tile_rows[MAX_TILES];
__device__ int   g_ntiles;

__device__ __half g_xh  [(size_t)TOKENS * HIDDEN];        // fp16 x
__device__ __half g_wgph[(size_t)NEXP * INTER * HIDDEN];  // fp16 gate proj
__device__ __half g_wuph[(size_t)NEXP * INTER * HIDDEN];  // fp16 up proj
__device__ __half g_wdph[(size_t)NEXP * HIDDEN * INTER];  // fp16 down proj
__device__ __half g_act [(size_t)NSLOTS * INTER];         // swiglu out (fp16)
__device__ float  g_dout[(size_t)NSLOTS * HIDDEN];        // unweighted expert rows

// ---------------- helpers ----------------
__device__ __forceinline__ uint32_t smem_u32(const void* p) {
    uint32_t a;
    asm("{ .reg .u64 t; cvta.to.shared.u64 t, %1; cvt.u32.u64 %0, t; }" : "=r"(a) : "l"(p));
    return a;
}
__device__ __forceinline__ void cp16(uint32_t dst, const void* src, int src_sz) {
    asm volatile("cp.async.cg.shared.global [%0], [%1], 16, %2;\n"
                 :: "r"(dst), "l"(src), "r"(src_sz) : "memory");
}
__device__ __forceinline__ void cp_commit() {
    asm volatile("cp.async.commit_group;\n" ::: "memory");
}
__device__ __forceinline__ void cp_wait2() {
    asm volatile("cp.async.wait_group 2;\n" ::: "memory");
}
// f16 MMA: D(f32) += A(f16) * B(f16)
__device__ __forceinline__ void mma_f16(float* c, const uint32_t* a, const uint32_t* b) {
    asm volatile(
        "mma.sync.aligned.m16n8k16.row.col.f32.f16.f16.f32 "
        "{%0,%1,%2,%3},{%4,%5,%6,%7},{%8,%9},{%0,%1,%2,%3};"
        : "+f"(c[0]), "+f"(c[1]), "+f"(c[2]), "+f"(c[3])
        : "r"(a[0]), "r"(a[1]), "r"(a[2]), "r"(a[3]), "r"(b[0]), "r"(b[1]));
}
// word index inside a [rows][32-word] tile (word = 2 fp16), XOR-swizzled
__device__ __forceinline__ int swz(int row, int col) {
    return row * 32 + ((col & 3) | ((((col >> 2) ^ row) & 7) << 2));
}

// ---------------- routing ----------------
__global__ void k_zero() { if (threadIdx.x < NEXP) g_cnt[threadIdx.x] = 0; }

__global__ void k_route(const float* __restrict__ x, const float* __restrict__ wg) {
    __shared__ float s_wg[NEXP * HIDDEN];
    int tid = threadIdx.x;
    for (int i = tid * 4; i < NEXP * HIDDEN; i += blockDim.x * 4)
        *(float4*)&s_wg[i] = *(const float4*)&wg[i];
    __syncthreads();
    int warp = tid >> 5, lane = tid & 31;
    int t = blockIdx.x * 8 + warp;
    float p[NEXP];
#pragma unroll
    for (int e = 0; e < NEXP; e++) p[e] = 0.f;
    const float* xr = x + (size_t)t * HIDDEN;
    for (int k = lane; k < HIDDEN; k += 32) {
        float xv = xr[k];
#pragma unroll
        for (int e = 0; e < NEXP; e++) p[e] += xv * s_wg[e * HIDDEN + k];
    }
#pragma unroll
    for (int e = 0; e < NEXP; e++)
#pragma unroll
        for (int o = 16; o; o >>= 1) p[e] += __shfl_xor_sync(0xffffffffu, p[e], o);
    if (lane == 0) {
        int e0 = 0;
#pragma unroll
        for (int e = 1; e < NEXP; e++) if (p[e] > p[e0]) e0 = e;
        int e1 = -1; float v1 = -1e30f;
#pragma unroll
        for (int e = 0; e < NEXP; e++) {
            if (e == e0) continue;
            if (e1 < 0 || p[e] > v1) { e1 = e; v1 = p[e]; }
        }
        float b = __expf(v1 - p[e0]);
        float inv = 1.f / (1.f + b);
        g_e0[t] = e0; g_e1[t] = e1;
        g_w0[t] = inv; g_w1[t] = b * inv;
        atomicAdd(&g_cnt[e0], 1);
        atomicAdd(&g_cnt[e1], 1);
    }
}

__global__ void k_plan() {
    if (threadIdx.x == 0) {
        int off = 0, nt = 0;
        for (int e = 0; e < NEXP; e++) {
            g_off[e] = off;
            int c = g_cnt[e];
            int m0 = 0;
            while (m0 < c) {
                g_tile_e[nt] = e;
                g_tile_m0[nt] = off + m0;
                g_tile_rows[nt] = min(BM, c - m0);
                m0 += BM; nt++;
            }
            off += c;
            g_cur[e] = 0;
        }
        g_off[NEXP] = off;
        g_ntiles = nt;
    }
}

__global__ void k_scatter() {
    int t = blockIdx.x * blockDim.x + threadIdx.x;
    if (t >= TOKENS) return;
    int e0 = g_e0[t], e1 = g_e1[t];
    int i0 = g_off[e0] + atomicAdd(&g_cur[e0], 1);
    g_row_token[i0] = t; g_slot0[t] = i0;
    int i1 = g_off[e1] + atomicAdd(&g_cur[e1], 1);
    g_row_token[i1] = t; g_slot1[t] = i1;
}

// ---------------- merged fp32 -> fp16 conversion (one launch) ----------------
#define NX4 ((TOKENS * HIDDEN) / 4)
#define NW4 ((NEXP * INTER * HIDDEN) / 4)
__global__ void k_cvt(const float* __restrict__ x,
                      const float* __restrict__ wgp,
                      const float* __restrict__ wup,
                      const float* __restrict__ wdp) {
    long long i = (long long)blockIdx.x * blockDim.x + threadIdx.x;
    const float* src; __half* dst; long long j;
    if (i < NX4)                { src = x;   dst = g_xh;   j = i; }
    else if (i < NX4 + NW4)     { src = wgp; dst = g_wgph; j = i - NX4; }
    else if (i < NX4 + 2*NW4)   { src = wup; dst = g_wuph; j = i - NX4 - NW4; }
    else if (i < NX4 + 3*NW4)   { src = wdp; dst = g_wdph; j = i - NX4 - 2*NW4; }
    else return;
    float4 v = ((const float4*)src)[j];
    __half2 h01 = __floats2half2_rn(v.x, v.y);
    __half2 h23 = __floats2half2_rn(v.z, v.w);
    uint2 o;
    o.x = *(uint32_t*)&h01;
    o.y = *(uint32_t*)&h23;
    ((uint2*)dst)[j] = o;
}

// ---------------- K4: gate+up GEMM + SwiGLU (fp16 MMA) ----------------
// block 128(tok) x 128(inter) for BOTH gate and up; 8 warps 2(m) x 4(n),
// warp tile 64x32 per matrix; BK=64 fp16; 3-stage cp.async ring.
// stage = A[128x64 h] 16KB | G[128x64 h] 16KB | U[128x64 h] 16KB = 48KB
__global__ void __launch_bounds__(256, 1)
k_gateup() {
    int bt = blockIdx.y;
    if (bt >= g_ntiles) return;
    int e = g_tile_e[bt], m0 = g_tile_m0[bt], rows = g_tile_rows[bt];
    int n0 = blockIdx.x * 128;

    extern __shared__ uint32_t dsm[];
    const int STAGE_W = 12288;           // words (uint32) per stage
    uint32_t sbase = smem_u32(dsm);

    int tid = threadIdx.x, warp = tid >> 5, lane = tid & 31;
    int wm = warp & 1, wn = warp >> 1;

    const __half* wg_e = g_wgph + (size_t)e * INTER * HIDDEN;
    const __half* wu_e = g_wuph + (size_t)e * INTER * HIDDEN;

    // 4 x 16B chunks per array per thread; 8 chunks (16B) per 128B row
    const __half* a_src[4]; int a_sz[4];
    const __half* bg_src[4]; const __half* bu_src[4];
    uint32_t soff[4];
#pragma unroll
    for (int i = 0; i < 4; i++) {
        int c = tid + 256 * i;
        int r = c >> 3, c8 = c & 7;
        bool v = r < rows;
        int tok = v ? g_row_token[m0 + r] : 0;
        a_src[i] = g_xh + (size_t)tok * HIDDEN + c8 * 8;
        a_sz[i] = v ? 16 : 0;
        bg_src[i] = wg_e + (size_t)(n0 + r) * HIDDEN + c8 * 8;
        bu_src[i] = wu_e + (size_t)(n0 + r) * HIDDEN + c8 * 8;
        soff[i] = (uint32_t)(r * 128 + ((c8 ^ (r & 7)) << 4));
    }

    float accG[4][4][4], accU[4][4][4];
#pragma unroll
    for (int a = 0; a < 4; a++)
#pragma unroll
        for (int b = 0; b < 4; b++)
#pragma unroll
            for (int q = 0; q < 4; q++) { accG[a][b][q] = 0.f; accU[a][b][q] = 0.f; }

    auto load_stage = [&](int kt, int buf) {
        uint32_t base = sbase + (uint32_t)(buf * STAGE_W) * 4u;
#pragma unroll
        for (int i = 0; i < 4; i++) {
            cp16(base + soff[i],          a_src[i]  + kt * 64, a_sz[i]);
            cp16(base + 16384u + soff[i], bg_src[i] + kt * 64, 16);
            cp16(base + 32768u + soff[i], bu_src[i] + kt * 64, 16);
        }
    };

    load_stage(0, 0); cp_commit();
    load_stage(1, 1); cp_commit();
    load_stage(2, 2); cp_commit();

    const int KT = HIDDEN / 64;  // 16
    for (int kt = 0; kt < KT; kt++) {
        int buf = kt % 3;
        cp_wait2();
        __syncthreads();

        const uint32_t* sA = dsm + buf * STAGE_W;
        const uint32_t* sG = sA + 4096;
        const uint32_t* sU = sG + 4096;

#pragma unroll
        for (int s = 0; s < 4; s++) {     // 4 k16-steps per BK=64
            uint32_t af[4][4];
#pragma unroll
            for (int mi = 0; mi < 4; mi++) {
                int row = wm * 64 + mi * 16 + (lane >> 2);
                int col = s * 8 + (lane & 3);
                af[mi][0] = sA[swz(row,     col)];
                af[mi][1] = sA[swz(row + 8, col)];
                af[mi][2] = sA[swz(row,     col + 4)];
                af[mi][3] = sA[swz(row + 8, col + 4)];
            }
            uint32_t bg[4][2], bu[4][2];
#pragma unroll
            for (int ni = 0; ni < 4; ni++) {
                int nr = wn * 32 + ni * 8 + (lane >> 2);
                int col = s * 8 + (lane & 3);
                bg[ni][0] = sG[swz(nr, col)];
                bg[ni][1] = sG[swz(nr, col + 4)];
                bu[ni][0] = sU[swz(nr, col)];
                bu[ni][1] = sU[swz(nr, col + 4)];
            }
#pragma unroll
            for (int mi = 0; mi < 4; mi++)
#pragma unroll
                for (int ni = 0; ni < 4; ni++) {
                    mma_f16(accG[mi][ni], af[mi], bg[ni]);
                    mma_f16(accU[mi][ni], af[mi], bu[ni]);
                }
        }
        __syncthreads();
        if (kt + 3 < KT) load_stage(kt + 3, buf);
        cp_commit();
    }

    // epilogue: act = fp16(silu(g) * u)
#pragma unroll
    for (int mi = 0; mi < 4; mi++) {
        int r_lo = wm * 64 + mi * 16 + (lane >> 2);
#pragma unroll
        for (int half = 0; half < 2; half++) {
            int row = r_lo + half * 8;
            if (row >= rows) continue;
            __half* arow = g_act + (size_t)(m0 + row) * INTER;
#pragma unroll
            for (int ni = 0; ni < 4; ni++) {
                int coln = n0 + wn * 32 + ni * 8 + (lane & 3) * 2;
                float g0 = accG[mi][ni][half * 2 + 0];
                float g1 = accG[mi][ni][half * 2 + 1];
                float u0 = accU[mi][ni][half * 2 + 0];
                float u1 = accU[mi][ni][half * 2 + 1];
                float s0 = g0 / (1.f + __expf(-g0)) * u0;
                float s1 = g1 / (1.f + __expf(-g1)) * u1;
                __half2 h = __floats2half2_rn(s0, s1);
                *(__half2*)&arow[coln] = h;
            }
        }
    }
}

// ---------------- K5: down GEMM (fp16 MMA) -> unweighted fp32 rows ----------------
// block 128(slots) x 256(hidden); 8 warps 2(m) x 4(n), warp tile 64x64; BK=64.
// stage = A[128x64 h] 16KB | B[256x64 h] 32KB = 48KB
__global__ void __launch_bounds__(256, 1)
k_down() {
    int bt = blockIdx.y;
    if (bt >= g_ntiles) return;
    int e = g_tile_e[bt], m0 = g_tile_m0[bt], rows = g_tile_rows[bt];
    int n0 = blockIdx.x * 256;

    extern __shared__ uint32_t dsm[];
    const int STAGE_W = 12288;
    uint32_t sbase = smem_u32(dsm);

    int tid = threadIdx.x, warp = tid >> 5, lane = tid & 31;
    int wm = warp & 1, wn = warp >> 1;

    const __half* wd_e = g_wdph + (size_t)e * HIDDEN * INTER;

    const __half* a_src[4]; int a_sz[4]; uint32_t a_off[4];
    const __half* b_src[8]; uint32_t b_off[8];
#pragma unroll
    for (int i = 0; i < 4; i++) {
        int c = tid + 256 * i;
        int r = c >> 3, c8 = c & 7;
        bool v = r < rows;
        a_src[i] = g_act + (size_t)(m0 + (v ? r : 0)) * INTER + c8 * 8;
        a_sz[i] = v ? 16 : 0;
        a_off[i] = (uint32_t)(r * 128 + ((c8 ^ (r & 7)) << 4));
    }
#pragma unroll
    for (int i = 0; i < 8; i++) {
        int c = tid + 256 * i;
        int r = c >> 3, c8 = c & 7;
        b_src[i] = wd_e + (size_t)(n0 + r) * INTER + c8 * 8;
        b_off[i] = (uint32_t)(r * 128 + ((c8 ^ (r & 7)) << 4));
    }

    float acc[4][8][4];
#pragma unroll
    for (int a = 0; a < 4; a++)
#pragma unroll
        for (int b = 0; b < 8; b++)
#pragma unroll
            for (int q = 0; q < 4; q++) acc[a][b][q] = 0.f;

    auto load_stage = [&](int kt, int buf) {
        uint32_t base = sbase + (uint32_t)(buf * STAGE_W) * 4u;
#pragma unroll
        for (int i = 0; i < 4; i++)
            cp16(base + a_off[i], a_src[i] + kt * 64, a_sz[i]);
#pragma unroll
        for (int i = 0; i < 8; i++)
            cp16(base + 16384u + b_off[i], b_src[i] + kt * 64, 16);
    };

    load_stage(0, 0); cp_commit();
    load_stage(1, 1); cp_commit();
    load_stage(2, 2); cp_commit();

    const int KT = INTER / 64;  // 44
    for (int kt = 0; kt < KT; kt++) {
        int buf = kt % 3;
        cp_wait2();
        __syncthreads();

        const uint32_t* sA = dsm + buf * STAGE_W;
        const uint32_t* sB = sA + 4096;

#pragma unroll
        for (int s = 0; s < 4; s++) {
            uint32_t af[4][4];
#pragma unroll
            for (int mi = 0; mi < 4; mi++) {
                int row = wm * 64 + mi * 16 + (lane >> 2);
                int col = s * 8 + (lane & 3);
                af[mi][0] = sA[swz(row,     col)];
                af[mi][1] = sA[swz(row + 8, col)];
                af[mi][2] = sA[swz(row,     col + 4)];
                af[mi][3] = sA[swz(row + 8, col + 4)];
            }
            uint32_t bf[8][2];
#pragma unroll
            for (int ni = 0; ni < 8; ni++) {
                int nr = wn * 64 + ni * 8 + (lane >> 2);
                int col = s * 8 + (lane & 3);
                bf[ni][0] = sB[swz(nr, col)];
                bf[ni][1] = sB[swz(nr, col + 4)];
            }
#pragma unroll
            for (int mi = 0; mi < 4; mi++)
#pragma unroll
                for (int ni = 0; ni < 8; ni++)
                    mma_f16(acc[mi][ni], af[mi], bf[ni]);
        }
        __syncthreads();
        if (kt + 3 < KT) load_stage(kt + 3, buf);
        cp_commit();
    }

    // epilogue: unweighted rows -> g_dout (fp32)
#pragma unroll
    for (int mi = 0; mi < 4; mi++) {
        int r_lo = wm * 64 + mi * 16 + (lane >> 2);
#pragma unroll
        for (int half = 0; half < 2; half++) {
            int row = r_lo + half * 8;
            if (row >= rows) continue;
            float* orow = g_dout + (size_t)(m0 + row) * HIDDEN;
#pragma unroll
            for (int ni = 0; ni < 8; ni++) {
                int coln = n0 + wn * 64 + ni * 8 + (lane & 3) * 2;
                float2 o;
                o.x = acc[mi][ni][half * 2 + 0];
                o.y = acc[mi][ni][half * 2 + 1];
                *(float2*)&orow[coln] = o;
            }
        }
    }
}

// ---------------- combine ----------------
__global__ void k_combine(float* __restrict__ out) {
    int t = blockIdx.x, j = threadIdx.x;
    int s0 = g_slot0[t], s1 = g_slot1[t];
    float w0 = g_w0[t], w1 = g_w1[t];
    float4 a = ((const float4*)(g_dout + (size_t)s0 * HIDDEN))[j];
    float4 b = ((const float4*)(g_dout + (size_t)s1 * HIDDEN))[j];
    float4 o;
    o.x = w0 * a.x + w1 * b.x;
    o.y = w0 * a.y + w1 * b.y;
    o.z = w0 * a.z + w1 * b.z;
    o.w = w0 * a.w + w1 * b.w;
    ((float4*)(out + (size_t)t * HIDDEN))[j] = o;
}

// ---------------- launch ----------------
extern "C" void kernel_launch(void* const* d_in, const int* in_sizes, int n_in,
                              void* d_out, int out_size) {
    const float* x   = (const float*)d_in[0];
    const float* wg  = (const float*)d_in[1];
    const float* wgp = (const float*)d_in[2];
    const float* wup = (const float*)d_in[3];
    const float* wdp = (const float*)d_in[4];
    float* out = (float*)d_out;

    const int SMEM_DYN = 3 * 12288 * 4;  // 147456 B
    cudaFuncSetAttribute(k_gateup, cudaFuncAttributeMaxDynamicSharedMemorySize, SMEM_DYN);
    cudaFuncSetAttribute(k_down,   cudaFuncAttributeMaxDynamicSharedMemorySize, SMEM_DYN);

    // launch order chosen so k_gateup is the 6th launch (ncu -s 5 -c 1 captures it)
    k_zero<<<1, 32>>>();
    k_route<<<TOKENS / 8, 256>>>(x, wg);
    k_plan<<<1, 1>>>();
    k_scatter<<<TOKENS / 256, 256>>>();

    long long ncvt = (long long)NX4 + 3LL * NW4;
    k_cvt<<<(unsigned)((ncvt + 255) / 256), 256>>>(x, wgp, wup, wdp);

    k_gateup<<<dim3(INTER / 128, 136), 256, SMEM_DYN>>>();
    k_down  <<<dim3(HIDDEN / 256, 136), 256, SMEM_DYN>>>();
    k_combine<<<TOKENS, 256>>>(out);
}

// round 5
// speedup vs baseline: 2.1486x; 1.0638x over previous
#include <cuda_runtime.h>
#include <cuda_fp16.h>
#include <cstdint>

#define TOKENS 8192
#define HIDDEN 1024
#define INTER  2816
#define NEXP   8
#define NSLOTS (2*TOKENS)
#define MAX_TILES 160
#define BM 128

// ---------------- device scratch ----------------
__device__ int   g_cnt[NEXP];
__device__ int   g_cur[NEXP];
__device__ int   g_off[NEXP + 1];
__device__ int   g_e0[TOKENS];
__device__ int   g_e1[TOKENS];
__device__ float g_w0[TOKENS];
__device__ float g_w1[TOKENS];
__device__ int   g_row_token[NSLOTS];
__device__ int   g_slot0[TOKENS];
__device__ int   g_slot1[TOKENS];
__device__ int   g_tile_e[MAX_TILES];
__device__ int   g_tile_m0[MAX_TILES];
__device__ int   g_tile_rows[MAX_TILES];
__device__ int   g_ntiles;

__device__ __half g_xh  [(size_t)TOKENS * HIDDEN];
__device__ __half g_wgph[(size_t)NEXP * INTER * HIDDEN];
__device__ __half g_wuph[(size_t)NEXP * INTER * HIDDEN];
__device__ __half g_wdph[(size_t)NEXP * HIDDEN * INTER];
__device__ __half g_act [(size_t)NSLOTS * INTER];
__device__ float  g_dout[(size_t)NSLOTS * HIDDEN];

// ---------------- helpers ----------------
__device__ __forceinline__ uint32_t smem_u32(const void* p) {
    uint32_t a;
    asm("{ .reg .u64 t; cvta.to.shared.u64 t, %1; cvt.u32.u64 %0, t; }" : "=r"(a) : "l"(p));
    return a;
}
__device__ __forceinline__ void cp16(uint32_t dst, const void* src, int src_sz) {
    asm volatile("cp.async.cg.shared.global [%0], [%1], 16, %2;\n"
                 :: "r"(dst), "l"(src), "r"(src_sz) : "memory");
}
__device__ __forceinline__ void cp_commit() {
    asm volatile("cp.async.commit_group;\n" ::: "memory");
}
__device__ __forceinline__ void cp_wait2() {
    asm volatile("cp.async.wait_group 2;\n" ::: "memory");
}
__device__ __forceinline__ void mma_f16(float* c, const uint32_t* a, const uint32_t* b) {
    asm volatile(
        "mma.sync.aligned.m16n8k16.row.col.f32.f16.f16.f32 "
        "{%0,%1,%2,%3},{%4,%5,%6,%7},{%8,%9},{%0,%1,%2,%3};"
        : "+f"(c[0]), "+f"(c[1]), "+f"(c[2]), "+f"(c[3])
        : "r"(a[0]), "r"(a[1]), "r"(a[2]), "r"(a[3]), "r"(b[0]), "r"(b[1]));
}
__device__ __forceinline__ void ldsm_x4(uint32_t* r, uint32_t addr) {
    asm volatile("ldmatrix.sync.aligned.m8n8.x4.shared.b16 {%0,%1,%2,%3}, [%4];"
                 : "=r"(r[0]), "=r"(r[1]), "=r"(r[2]), "=r"(r[3]) : "r"(addr));
}

// ---------------- routing ----------------
__global__ void k_zero() { if (threadIdx.x < NEXP) g_cnt[threadIdx.x] = 0; }

__global__ void k_route(const float* __restrict__ x, const float* __restrict__ wg) {
    __shared__ float s_wg[NEXP * HIDDEN];
    int tid = threadIdx.x;
    for (int i = tid * 4; i < NEXP * HIDDEN; i += blockDim.x * 4)
        *(float4*)&s_wg[i] = *(const float4*)&wg[i];
    __syncthreads();
    int warp = tid >> 5, lane = tid & 31;
    int t = blockIdx.x * 8 + warp;
    float p[NEXP];
#pragma unroll
    for (int e = 0; e < NEXP; e++) p[e] = 0.f;
    const float* xr = x + (size_t)t * HIDDEN;
    for (int k = lane; k < HIDDEN; k += 32) {
        float xv = xr[k];
#pragma unroll
        for (int e = 0; e < NEXP; e++) p[e] += xv * s_wg[e * HIDDEN + k];
    }
#pragma unroll
    for (int e = 0; e < NEXP; e++)
#pragma unroll
        for (int o = 16; o; o >>= 1) p[e] += __shfl_xor_sync(0xffffffffu, p[e], o);
    if (lane == 0) {
        int e0 = 0;
#pragma unroll
        for (int e = 1; e < NEXP; e++) if (p[e] > p[e0]) e0 = e;
        int e1 = -1; float v1 = -1e30f;
#pragma unroll
        for (int e = 0; e < NEXP; e++) {
            if (e == e0) continue;
            if (e1 < 0 || p[e] > v1) { e1 = e; v1 = p[e]; }
        }
        float b = __expf(v1 - p[e0]);
        float inv = 1.f / (1.f + b);
        g_e0[t] = e0; g_e1[t] = e1;
        g_w0[t] = inv; g_w1[t] = b * inv;
        atomicAdd(&g_cnt[e0], 1);
        atomicAdd(&g_cnt[e1], 1);
    }
}

__global__ void k_plan() {
    if (threadIdx.x == 0) {
        int off = 0, nt = 0;
        for (int e = 0; e < NEXP; e++) {
            g_off[e] = off;
            int c = g_cnt[e];
            int m0 = 0;
            while (m0 < c) {
                g_tile_e[nt] = e;
                g_tile_m0[nt] = off + m0;
                g_tile_rows[nt] = min(BM, c - m0);
                m0 += BM; nt++;
            }
            off += c;
            g_cur[e] = 0;
        }
        g_off[NEXP] = off;
        g_ntiles = nt;
    }
}

__global__ void k_scatter() {
    int t = blockIdx.x * blockDim.x + threadIdx.x;
    if (t >= TOKENS) return;
    int e0 = g_e0[t], e1 = g_e1[t];
    int i0 = g_off[e0] + atomicAdd(&g_cur[e0], 1);
    g_row_token[i0] = t; g_slot0[t] = i0;
    int i1 = g_off[e1] + atomicAdd(&g_cur[e1], 1);
    g_row_token[i1] = t; g_slot1[t] = i1;
}

// ---------------- merged fp32 -> fp16 conversion ----------------
#define NX4 ((TOKENS * HIDDEN) / 4)
#define NW4 ((NEXP * INTER * HIDDEN) / 4)
__global__ void k_cvt(const float* __restrict__ x,
                      const float* __restrict__ wgp,
                      const float* __restrict__ wup,
                      const float* __restrict__ wdp) {
    long long i = (long long)blockIdx.x * blockDim.x + threadIdx.x;
    const float* src; __half* dst; long long j;
    if (i < NX4)                { src = x;   dst = g_xh;   j = i; }
    else if (i < NX4 + NW4)     { src = wgp; dst = g_wgph; j = i - NX4; }
    else if (i < NX4 + 2*NW4)   { src = wup; dst = g_wuph; j = i - NX4 - NW4; }
    else if (i < NX4 + 3*NW4)   { src = wdp; dst = g_wdph; j = i - NX4 - 2*NW4; }
    else return;
    float4 v = ((const float4*)src)[j];
    __half2 h01 = __floats2half2_rn(v.x, v.y);
    __half2 h23 = __floats2half2_rn(v.z, v.w);
    uint2 o;
    o.x = *(uint32_t*)&h01;
    o.y = *(uint32_t*)&h23;
    ((uint2*)dst)[j] = o;
}

// ---------------- K4: gate+up GEMM + SwiGLU (fp16 MMA + ldmatrix) ----------------
// block 128(tok) x 128(inter); 8 warps 2(m) x 4(n); warp tile 64x32 per matrix;
// BK=64; 3-stage cp.async ring; stage = A 16KB | G 16KB | U 16KB.
__global__ void __launch_bounds__(256, 1)
k_gateup() {
    int bt = blockIdx.y;
    if (bt >= g_ntiles) return;
    int e = g_tile_e[bt], m0 = g_tile_m0[bt], rows = g_tile_rows[bt];
    int n0 = blockIdx.x * 128;

    extern __shared__ uint32_t dsm[];
    uint32_t sbase = smem_u32(dsm);

    int tid = threadIdx.x, warp = tid >> 5, lane = tid & 31;
    int wm = warp & 1, wn = warp >> 1;

    const __half* wg_e = g_wgph + (size_t)e * INTER * HIDDEN;
    const __half* wu_e = g_wuph + (size_t)e * INTER * HIDDEN;

    const __half* a_src[4]; int a_sz[4];
    const __half* bg_src[4]; const __half* bu_src[4];
    uint32_t soff[4];
#pragma unroll
    for (int i = 0; i < 4; i++) {
        int c = tid + 256 * i;
        int r = c >> 3, c8 = c & 7;
        bool v = r < rows;
        int tok = v ? g_row_token[m0 + r] : 0;
        a_src[i] = g_xh + (size_t)tok * HIDDEN + c8 * 8;
        a_sz[i] = v ? 16 : 0;
        bg_src[i] = wg_e + (size_t)(n0 + r) * HIDDEN + c8 * 8;
        bu_src[i] = wu_e + (size_t)(n0 + r) * HIDDEN + c8 * 8;
        soff[i] = (uint32_t)(r * 128 + ((c8 ^ (r & 7)) << 4));
    }

    // ldmatrix per-lane row bases (byte offsets within a tile)
    int lr = lane & 7, grp = lane >> 3;
    int rsel = (grp & 1) << 3;     // +8 rows for groups 1,3
    int khalf = grp >> 1;          // +1 16B-chunk for groups 2,3
    uint32_t a_row[4], b_row[2];
#pragma unroll
    for (int mi = 0; mi < 4; mi++)
        a_row[mi] = (uint32_t)((wm * 64 + mi * 16 + rsel + lr) * 128);
#pragma unroll
    for (int pi = 0; pi < 2; pi++)
        b_row[pi] = (uint32_t)((wn * 32 + pi * 16 + rsel + lr) * 128);

    float accG[4][4][4], accU[4][4][4];
#pragma unroll
    for (int a = 0; a < 4; a++)
#pragma unroll
        for (int b = 0; b < 4; b++)
#pragma unroll
            for (int q = 0; q < 4; q++) { accG[a][b][q] = 0.f; accU[a][b][q] = 0.f; }

    auto load_stage = [&](int kt, int buf) {
        uint32_t base = sbase + (uint32_t)buf * 49152u;
#pragma unroll
        for (int i = 0; i < 4; i++) {
            cp16(base + soff[i],          a_src[i]  + kt * 64, a_sz[i]);
            cp16(base + 16384u + soff[i], bg_src[i] + kt * 64, 16);
            cp16(base + 32768u + soff[i], bu_src[i] + kt * 64, 16);
        }
    };

    load_stage(0, 0); cp_commit();
    load_stage(1, 1); cp_commit();
    load_stage(2, 2); cp_commit();

    const int KT = HIDDEN / 64;  // 16
    for (int kt = 0; kt < KT; kt++) {
        int buf = kt % 3;
        cp_wait2();
        __syncthreads();

        uint32_t bb = sbase + (uint32_t)buf * 49152u;

#pragma unroll
        for (int s = 0; s < 4; s++) {
            uint32_t xw = (uint32_t)((((2 * s + khalf) ^ lr) << 4));
            uint32_t af[4][4];
#pragma unroll
            for (int mi = 0; mi < 4; mi++)
                ldsm_x4(af[mi], bb + a_row[mi] + xw);

            uint32_t bgf[4][2], buf16[4][2];
#pragma unroll
            for (int pi = 0; pi < 2; pi++) {
                uint32_t t4[4];
                ldsm_x4(t4, bb + 16384u + b_row[pi] + xw);
                bgf[2*pi][0] = t4[0]; bgf[2*pi+1][0] = t4[1];
                bgf[2*pi][1] = t4[2]; bgf[2*pi+1][1] = t4[3];
                ldsm_x4(t4, bb + 32768u + b_row[pi] + xw);
                buf16[2*pi][0] = t4[0]; buf16[2*pi+1][0] = t4[1];
                buf16[2*pi][1] = t4[2]; buf16[2*pi+1][1] = t4[3];
            }
#pragma unroll
            for (int mi = 0; mi < 4; mi++)
#pragma unroll
                for (int ni = 0; ni < 4; ni++) {
                    mma_f16(accG[mi][ni], af[mi], bgf[ni]);
                    mma_f16(accU[mi][ni], af[mi], buf16[ni]);
                }
        }
        __syncthreads();
        if (kt + 3 < KT) load_stage(kt + 3, buf);
        cp_commit();
    }

    // epilogue: act = fp16(silu(g) * u)
#pragma unroll
    for (int mi = 0; mi < 4; mi++) {
        int r_lo = wm * 64 + mi * 16 + (lane >> 2);
#pragma unroll
        for (int half = 0; half < 2; half++) {
            int row = r_lo + half * 8;
            if (row >= rows) continue;
            __half* arow = g_act + (size_t)(m0 + row) * INTER;
#pragma unroll
            for (int ni = 0; ni < 4; ni++) {
                int coln = n0 + wn * 32 + ni * 8 + (lane & 3) * 2;
                float g0 = accG[mi][ni][half * 2 + 0];
                float g1 = accG[mi][ni][half * 2 + 1];
                float u0 = accU[mi][ni][half * 2 + 0];
                float u1 = accU[mi][ni][half * 2 + 1];
                float s0 = g0 / (1.f + __expf(-g0)) * u0;
                float s1 = g1 / (1.f + __expf(-g1)) * u1;
                __half2 h = __floats2half2_rn(s0, s1);
                *(__half2*)&arow[coln] = h;
            }
        }
    }
}

// ---------------- K5: down GEMM (fp16 MMA + ldmatrix) ----------------
// block 128(slots) x 256(hidden); 8 warps 2(m) x 4(n), warp tile 64x64; BK=64.
__global__ void __launch_bounds__(256, 1)
k_down() {
    int bt = blockIdx.y;
    if (bt >= g_ntiles) return;
    int e = g_tile_e[bt], m0 = g_tile_m0[bt], rows = g_tile_rows[bt];
    int n0 = blockIdx.x * 256;

    extern __shared__ uint32_t dsm[];
    uint32_t sbase = smem_u32(dsm);

    int tid = threadIdx.x, warp = tid >> 5, lane = tid & 31;
    int wm = warp & 1, wn = warp >> 1;

    const __half* wd_e = g_wdph + (size_t)e * HIDDEN * INTER;

    const __half* a_src[4]; int a_sz[4]; uint32_t a_off[4];
    const __half* b_src[8]; uint32_t b_off[8];
#pragma unroll
    for (int i = 0; i < 4; i++) {
        int c = tid + 256 * i;
        int r = c >> 3, c8 = c & 7;
        bool v = r < rows;
        a_src[i] = g_act + (size_t)(m0 + (v ? r : 0)) * INTER + c8 * 8;
        a_sz[i] = v ? 16 : 0;
        a_off[i] = (uint32_t)(r * 128 + ((c8 ^ (r & 7)) << 4));
    }
#pragma unroll
    for (int i = 0; i < 8; i++) {
        int c = tid + 256 * i;
        int r = c >> 3, c8 = c & 7;
        b_src[i] = wd_e + (size_t)(n0 + r) * INTER + c8 * 8;
        b_off[i] = (uint32_t)(r * 128 + ((c8 ^ (r & 7)) << 4));
    }

    int lr = lane & 7, grp = lane >> 3;
    int rsel = (grp & 1) << 3;
    int khalf = grp >> 1;
    uint32_t a_row[4], b_row[4];
#pragma unroll
    for (int mi = 0; mi < 4; mi++)
        a_row[mi] = (uint32_t)((wm * 64 + mi * 16 + rsel + lr) * 128);
#pragma unroll
    for (int pi = 0; pi < 4; pi++)
        b_row[pi] = (uint32_t)((wn * 64 + pi * 16 + rsel + lr) * 128);

    float acc[4][8][4];
#pragma unroll
    for (int a = 0; a < 4; a++)
#pragma unroll
        for (int b = 0; b < 8; b++)
#pragma unroll
            for (int q = 0; q < 4; q++) acc[a][b][q] = 0.f;

    auto load_stage = [&](int kt, int buf) {
        uint32_t base = sbase + (uint32_t)buf * 49152u;
#pragma unroll
        for (int i = 0; i < 4; i++)
            cp16(base + a_off[i], a_src[i] + kt * 64, a_sz[i]);
#pragma unroll
        for (int i = 0; i < 8; i++)
            cp16(base + 16384u + b_off[i], b_src[i] + kt * 64, 16);
    };

    load_stage(0, 0); cp_commit();
    load_stage(1, 1); cp_commit();
    load_stage(2, 2); cp_commit();

    const int KT = INTER / 64;  // 44
    for (int kt = 0; kt < KT; kt++) {
        int buf = kt % 3;
        cp_wait2();
        __syncthreads();

        uint32_t bb = sbase + (uint32_t)buf * 49152u;

#pragma unroll
        for (int s = 0; s < 4; s++) {
            uint32_t xw = (uint32_t)((((2 * s + khalf) ^ lr) << 4));
            uint32_t af[4][4];
#pragma unroll
            for (int mi = 0; mi < 4; mi++)
                ldsm_x4(af[mi], bb + a_row[mi] + xw);

            uint32_t bf[8][2];
#pragma unroll
            for (int pi = 0; pi < 4; pi++) {
                uint32_t t4[4];
                ldsm_x4(t4, bb + 16384u + b_row[pi] + xw);
                bf[2*pi][0] = t4[0]; bf[2*pi+1][0] = t4[1];
                bf[2*pi][1] = t4[2]; bf[2*pi+1][1] = t4[3];
            }
#pragma unroll
            for (int mi = 0; mi < 4; mi++)
#pragma unroll
                for (int ni = 0; ni < 8; ni++)
                    mma_f16(acc[mi][ni], af[mi], bf[ni]);
        }
        __syncthreads();
        if (kt + 3 < KT) load_stage(kt + 3, buf);
        cp_commit();
    }

#pragma unroll
    for (int mi = 0; mi < 4; mi++) {
        int r_lo = wm * 64 + mi * 16 + (lane >> 2);
#pragma unroll
        for (int half = 0; half < 2; half++) {
            int row = r_lo + half * 8;
            if (row >= rows) continue;
            float* orow = g_dout + (size_t)(m0 + row) * HIDDEN;
#pragma unroll
            for (int ni = 0; ni < 8; ni++) {
                int coln = n0 + wn * 64 + ni * 8 + (lane & 3) * 2;
                float2 o;
                o.x = acc[mi][ni][half * 2 + 0];
                o.y = acc[mi][ni][half * 2 + 1];
                *(float2*)&orow[coln] = o;
            }
        }
    }
}

// ---------------- combine ----------------
__global__ void k_combine(float* __restrict__ out) {
    int t = blockIdx.x, j = threadIdx.x;
    int s0 = g_slot0[t], s1 = g_slot1[t];
    float w0 = g_w0[t], w1 = g_w1[t];
    float4 a = ((const float4*)(g_dout + (size_t)s0 * HIDDEN))[j];
    float4 b = ((const float4*)(g_dout + (size_t)s1 * HIDDEN))[j];
    float4 o;
    o.x = w0 * a.x + w1 * b.x;
    o.y = w0 * a.y + w1 * b.y;
    o.z = w0 * a.z + w1 * b.z;
    o.w = w0 * a.w + w1 * b.w;
    ((float4*)(out + (size_t)t * HIDDEN))[j] = o;
}

// ---------------- launch ----------------
extern "C" void kernel_launch(void* const* d_in, const int* in_sizes, int n_in,
                              void* d_out, int out_size) {
    const float* x   = (const float*)d_in[0];
    const float* wg  = (const float*)d_in[1];
    const float* wgp = (const float*)d_in[2];
    const float* wup = (const float*)d_in[3];
    const float* wdp = (const float*)d_in[4];
    float* out = (float*)d_out;

    const int SMEM_DYN = 3 * 49152;  // 147456 B
    cudaFuncSetAttribute(k_gateup, cudaFuncAttributeMaxDynamicSharedMemorySize, SMEM_DYN);
    cudaFuncSetAttribute(k_down,   cudaFuncAttributeMaxDynamicSharedMemorySize, SMEM_DYN);

    k_zero<<<1, 32>>>();
    k_route<<<TOKENS / 8, 256>>>(x, wg);
    k_plan<<<1, 1>>>();
    k_scatter<<<TOKENS / 256, 256>>>();

    long long ncvt = (long long)NX4 + 3LL * NW4;
    k_cvt<<<(unsigned)((ncvt + 255) / 256), 256>>>(x, wgp, wup, wdp);

    k_gateup<<<dim3(INTER / 128, 136), 256, SMEM_DYN>>>();
    k_down  <<<dim3(HIDDEN / 256, 136), 256, SMEM_DYN>>>();
    k_combine<<<TOKENS, 256>>>(out);
}

// round 6
// speedup vs baseline: 2.2424x; 1.0437x over previous
#include <cuda_runtime.h>
#include <cuda_fp16.h>
#include <cstdint>

#define TOKENS 8192
#define HIDDEN 1024
#define INTER  2816
#define NEXP   8
#define NSLOTS (2*TOKENS)
#define MAX_TILES 160
#define BM 128

// ---------------- device scratch ----------------
__device__ int   g_cnt[NEXP];
__device__ int   g_cur[NEXP];
__device__ int   g_off[NEXP + 1];
__device__ int   g_e0[TOKENS];
__device__ int   g_e1[TOKENS];
__device__ float g_w0[TOKENS];
__device__ float g_w1[TOKENS];
__device__ int   g_row_token[NSLOTS];
__device__ int   g_slot0[TOKENS];
__device__ int   g_slot1[TOKENS];
__device__ int   g_tile_e[MAX_TILES];
__device__ int   g_tile_m0[MAX_TILES];
__device__ int   g_tile_rows[MAX_TILES];
__device__ int   g_ntiles;

__device__ __half g_xh  [(size_t)TOKENS * HIDDEN];
__device__ __half g_wgph[(size_t)NEXP * INTER * HIDDEN];
__device__ __half g_wuph[(size_t)NEXP * INTER * HIDDEN];
__device__ __half g_wdph[(size_t)NEXP * HIDDEN * INTER];
__device__ __half g_act [(size_t)NSLOTS * INTER];
__device__ float  g_dout[(size_t)NSLOTS * HIDDEN];

// ---------------- helpers ----------------
__device__ __forceinline__ uint32_t smem_u32(const void* p) {
    uint32_t a;
    asm("{ .reg .u64 t; cvta.to.shared.u64 t, %1; cvt.u32.u64 %0, t; }" : "=r"(a) : "l"(p));
    return a;
}
__device__ __forceinline__ void cp16(uint32_t dst, const void* src, int src_sz) {
    asm volatile("cp.async.cg.shared.global [%0], [%1], 16, %2;\n"
                 :: "r"(dst), "l"(src), "r"(src_sz) : "memory");
}
__device__ __forceinline__ void cp_commit() {
    asm volatile("cp.async.commit_group;\n" ::: "memory");
}
__device__ __forceinline__ void cp_wait2() {
    asm volatile("cp.async.wait_group 2;\n" ::: "memory");
}
__device__ __forceinline__ void mma_f16(float* c, const uint32_t* a, const uint32_t* b) {
    asm volatile(
        "mma.sync.aligned.m16n8k16.row.col.f32.f16.f16.f32 "
        "{%0,%1,%2,%3},{%4,%5,%6,%7},{%8,%9},{%0,%1,%2,%3};"
        : "+f"(c[0]), "+f"(c[1]), "+f"(c[2]), "+f"(c[3])
        : "r"(a[0]), "r"(a[1]), "r"(a[2]), "r"(a[3]), "r"(b[0]), "r"(b[1]));
}
__device__ __forceinline__ void ldsm_x4(uint32_t* r, uint32_t addr) {
    asm volatile("ldmatrix.sync.aligned.m8n8.x4.shared.b16 {%0,%1,%2,%3}, [%4];"
                 : "=r"(r[0]), "=r"(r[1]), "=r"(r[2]), "=r"(r[3]) : "r"(addr));
}

// ---------------- routing ----------------
__global__ void k_zero() { if (threadIdx.x < NEXP) g_cnt[threadIdx.x] = 0; }

__global__ void k_route(const float* __restrict__ x, const float* __restrict__ wg) {
    __shared__ float s_wg[NEXP * HIDDEN];
    int tid = threadIdx.x;
    for (int i = tid * 4; i < NEXP * HIDDEN; i += blockDim.x * 4)
        *(float4*)&s_wg[i] = *(const float4*)&wg[i];
    __syncthreads();
    int warp = tid >> 5, lane = tid & 31;
    int t = blockIdx.x * 8 + warp;
    float p[NEXP];
#pragma unroll
    for (int e = 0; e < NEXP; e++) p[e] = 0.f;
    const float* xr = x + (size_t)t * HIDDEN;
    for (int k = lane; k < HIDDEN; k += 32) {
        float xv = xr[k];
#pragma unroll
        for (int e = 0; e < NEXP; e++) p[e] += xv * s_wg[e * HIDDEN + k];
    }
#pragma unroll
    for (int e = 0; e < NEXP; e++)
#pragma unroll
        for (int o = 16; o; o >>= 1) p[e] += __shfl_xor_sync(0xffffffffu, p[e], o);
    if (lane == 0) {
        int e0 = 0;
#pragma unroll
        for (int e = 1; e < NEXP; e++) if (p[e] > p[e0]) e0 = e;
        int e1 = -1; float v1 = -1e30f;
#pragma unroll
        for (int e = 0; e < NEXP; e++) {
            if (e == e0) continue;
            if (e1 < 0 || p[e] > v1) { e1 = e; v1 = p[e]; }
        }
        float b = __expf(v1 - p[e0]);
        float inv = 1.f / (1.f + b);
        g_e0[t] = e0; g_e1[t] = e1;
        g_w0[t] = inv; g_w1[t] = b * inv;
        atomicAdd(&g_cnt[e0], 1);
        atomicAdd(&g_cnt[e1], 1);
    }
}

__global__ void k_plan() {
    if (threadIdx.x == 0) {
        int off = 0, nt = 0;
        for (int e = 0; e < NEXP; e++) {
            g_off[e] = off;
            int c = g_cnt[e];
            int m0 = 0;
            while (m0 < c) {
                g_tile_e[nt] = e;
                g_tile_m0[nt] = off + m0;
                g_tile_rows[nt] = min(BM, c - m0);
                m0 += BM; nt++;
            }
            off += c;
            g_cur[e] = 0;
        }
        g_off[NEXP] = off;
        g_ntiles = nt;
    }
}

__global__ void k_scatter() {
    int t = blockIdx.x * blockDim.x + threadIdx.x;
    if (t >= TOKENS) return;
    int e0 = g_e0[t], e1 = g_e1[t];
    int i0 = g_off[e0] + atomicAdd(&g_cur[e0], 1);
    g_row_token[i0] = t; g_slot0[t] = i0;
    int i1 = g_off[e1] + atomicAdd(&g_cur[e1], 1);
    g_row_token[i1] = t; g_slot1[t] = i1;
}

// ---------------- merged fp32 -> fp16 conversion ----------------
#define NX4 ((TOKENS * HIDDEN) / 4)
#define NW4 ((NEXP * INTER * HIDDEN) / 4)
__global__ void k_cvt(const float* __restrict__ x,
                      const float* __restrict__ wgp,
                      const float* __restrict__ wup,
                      const float* __restrict__ wdp) {
    long long i = (long long)blockIdx.x * blockDim.x + threadIdx.x;
    const float* src; __half* dst; long long j;
    if (i < NX4)                { src = x;   dst = g_xh;   j = i; }
    else if (i < NX4 + NW4)     { src = wgp; dst = g_wgph; j = i - NX4; }
    else if (i < NX4 + 2*NW4)   { src = wup; dst = g_wuph; j = i - NX4 - NW4; }
    else if (i < NX4 + 3*NW4)   { src = wdp; dst = g_wdph; j = i - NX4 - 2*NW4; }
    else return;
    float4 v = ((const float4*)src)[j];
    __half2 h01 = __floats2half2_rn(v.x, v.y);
    __half2 h23 = __floats2half2_rn(v.z, v.w);
    uint2 o;
    o.x = *(uint32_t*)&h01;
    o.y = *(uint32_t*)&h23;
    ((uint2*)dst)[j] = o;
}

// ---------------- K4: gate+up GEMM + SwiGLU (512 threads, 16 warps 4m x 4n) ----------------
// CTA tile 128(tok) x 128(inter) for BOTH matrices; warp tile 32x32 per matrix;
// BK=64; 3-stage ring; stage = A 16KB | G 16KB | U 16KB = 48KB.
__global__ void __launch_bounds__(512, 1)
k_gateup() {
    int bt = blockIdx.y;
    if (bt >= g_ntiles) return;
    int e = g_tile_e[bt], m0 = g_tile_m0[bt], rows = g_tile_rows[bt];
    int n0 = blockIdx.x * 128;

    extern __shared__ uint32_t dsm[];
    uint32_t sbase = smem_u32(dsm);

    int tid = threadIdx.x, warp = tid >> 5, lane = tid & 31;
    int wm = warp & 3, wn = warp >> 2;

    const __half* wg_e = g_wgph + (size_t)e * INTER * HIDDEN;
    const __half* wu_e = g_wuph + (size_t)e * INTER * HIDDEN;

    // per-thread load descriptors: 2 chunks per matrix (16B each)
    const __half* a_src[2]; int a_sz[2];
    const __half* bg_src[2]; const __half* bu_src[2];
    uint32_t soff[2];
#pragma unroll
    for (int i = 0; i < 2; i++) {
        int c = tid + 512 * i;
        int r = c >> 3, c8 = c & 7;
        bool v = r < rows;
        int tok = v ? g_row_token[m0 + r] : 0;
        a_src[i] = g_xh + (size_t)tok * HIDDEN + c8 * 8;
        a_sz[i] = v ? 16 : 0;
        bg_src[i] = wg_e + (size_t)(n0 + r) * HIDDEN + c8 * 8;
        bu_src[i] = wu_e + (size_t)(n0 + r) * HIDDEN + c8 * 8;
        soff[i] = (uint32_t)(r * 128 + ((c8 ^ (r & 7)) << 4));
    }

    // ldmatrix per-lane row bases
    int lr = lane & 7, grp = lane >> 3;
    int rsel = (grp & 1) << 3;
    int khalf = grp >> 1;
    uint32_t a_row[2], b_row[2];
#pragma unroll
    for (int mi = 0; mi < 2; mi++)
        a_row[mi] = (uint32_t)((wm * 32 + mi * 16 + rsel + lr) * 128);
#pragma unroll
    for (int pi = 0; pi < 2; pi++)
        b_row[pi] = (uint32_t)((wn * 32 + pi * 16 + rsel + lr) * 128);

    float accG[2][4][4], accU[2][4][4];
#pragma unroll
    for (int a = 0; a < 2; a++)
#pragma unroll
        for (int b = 0; b < 4; b++)
#pragma unroll
            for (int q = 0; q < 4; q++) { accG[a][b][q] = 0.f; accU[a][b][q] = 0.f; }

    auto load_stage = [&](int kt, int buf) {
        uint32_t base = sbase + (uint32_t)buf * 49152u;
#pragma unroll
        for (int i = 0; i < 2; i++) {
            cp16(base + soff[i],          a_src[i]  + kt * 64, a_sz[i]);
            cp16(base + 16384u + soff[i], bg_src[i] + kt * 64, 16);
            cp16(base + 32768u + soff[i], bu_src[i] + kt * 64, 16);
        }
    };

    load_stage(0, 0); cp_commit();
    load_stage(1, 1); cp_commit();
    load_stage(2, 2); cp_commit();

    const int KT = HIDDEN / 64;  // 16
    for (int kt = 0; kt < KT; kt++) {
        int buf = kt % 3;
        cp_wait2();
        __syncthreads();

        uint32_t bb = sbase + (uint32_t)buf * 49152u;

#pragma unroll
        for (int s = 0; s < 4; s++) {
            uint32_t xw = (uint32_t)((((2 * s + khalf) ^ lr) << 4));
            uint32_t af[2][4];
#pragma unroll
            for (int mi = 0; mi < 2; mi++)
                ldsm_x4(af[mi], bb + a_row[mi] + xw);

            uint32_t bgf[4][2], buf16[4][2];
#pragma unroll
            for (int pi = 0; pi < 2; pi++) {
                uint32_t t4[4];
                ldsm_x4(t4, bb + 16384u + b_row[pi] + xw);
                bgf[2*pi][0] = t4[0]; bgf[2*pi+1][0] = t4[1];
                bgf[2*pi][1] = t4[2]; bgf[2*pi+1][1] = t4[3];
                ldsm_x4(t4, bb + 32768u + b_row[pi] + xw);
                buf16[2*pi][0] = t4[0]; buf16[2*pi+1][0] = t4[1];
                buf16[2*pi][1] = t4[2]; buf16[2*pi+1][1] = t4[3];
            }
#pragma unroll
            for (int mi = 0; mi < 2; mi++)
#pragma unroll
                for (int ni = 0; ni < 4; ni++) {
                    mma_f16(accG[mi][ni], af[mi], bgf[ni]);
                    mma_f16(accU[mi][ni], af[mi], buf16[ni]);
                }
        }
        __syncthreads();
        if (kt + 3 < KT) load_stage(kt + 3, buf);
        cp_commit();
    }

    // epilogue: act = fp16(silu(g) * u)
#pragma unroll
    for (int mi = 0; mi < 2; mi++) {
        int r_lo = wm * 32 + mi * 16 + (lane >> 2);
#pragma unroll
        for (int half = 0; half < 2; half++) {
            int row = r_lo + half * 8;
            if (row >= rows) continue;
            __half* arow = g_act + (size_t)(m0 + row) * INTER;
#pragma unroll
            for (int ni = 0; ni < 4; ni++) {
                int coln = n0 + wn * 32 + ni * 8 + (lane & 3) * 2;
                float g0 = accG[mi][ni][half * 2 + 0];
                float g1 = accG[mi][ni][half * 2 + 1];
                float u0 = accU[mi][ni][half * 2 + 0];
                float u1 = accU[mi][ni][half * 2 + 1];
                float s0 = g0 / (1.f + __expf(-g0)) * u0;
                float s1 = g1 / (1.f + __expf(-g1)) * u1;
                __half2 h = __floats2half2_rn(s0, s1);
                *(__half2*)&arow[coln] = h;
            }
        }
    }
}

// ---------------- K5: down GEMM (512 threads, 16 warps 4m x 4n) ----------------
// CTA tile 128(slots) x 256(hidden); warp tile 32x64; BK=64; 3-stage ring;
// stage = A 16KB | B 32KB = 48KB.
__global__ void __launch_bounds__(512, 1)
k_down() {
    int bt = blockIdx.y;
    if (bt >= g_ntiles) return;
    int e = g_tile_e[bt], m0 = g_tile_m0[bt], rows = g_tile_rows[bt];
    int n0 = blockIdx.x * 256;

    extern __shared__ uint32_t dsm[];
    uint32_t sbase = smem_u32(dsm);

    int tid = threadIdx.x, warp = tid >> 5, lane = tid & 31;
    int wm = warp & 3, wn = warp >> 2;

    const __half* wd_e = g_wdph + (size_t)e * HIDDEN * INTER;

    const __half* a_src[2]; int a_sz[2]; uint32_t a_off[2];
    const __half* b_src[4]; uint32_t b_off[4];
#pragma unroll
    for (int i = 0; i < 2; i++) {
        int c = tid + 512 * i;
        int r = c >> 3, c8 = c & 7;
        bool v = r < rows;
        a_src[i] = g_act + (size_t)(m0 + (v ? r : 0)) * INTER + c8 * 8;
        a_sz[i] = v ? 16 : 0;
        a_off[i] = (uint32_t)(r * 128 + ((c8 ^ (r & 7)) << 4));
    }
#pragma unroll
    for (int i = 0; i < 4; i++) {
        int c = tid + 512 * i;
        int r = c >> 3, c8 = c & 7;
        b_src[i] = wd_e + (size_t)(n0 + r) * INTER + c8 * 8;
        b_off[i] = (uint32_t)(r * 128 + ((c8 ^ (r & 7)) << 4));
    }

    int lr = lane & 7, grp = lane >> 3;
    int rsel = (grp & 1) << 3;
    int khalf = grp >> 1;
    uint32_t a_row[2], b_row[4];
#pragma unroll
    for (int mi = 0; mi < 2; mi++)
        a_row[mi] = (uint32_t)((wm * 32 + mi * 16 + rsel + lr) * 128);
#pragma unroll
    for (int pi = 0; pi < 4; pi++)
        b_row[pi] = (uint32_t)((wn * 64 + pi * 16 + rsel + lr) * 128);

    float acc[2][8][4];
#pragma unroll
    for (int a = 0; a < 2; a++)
#pragma unroll
        for (int b = 0; b < 8; b++)
#pragma unroll
            for (int q = 0; q < 4; q++) acc[a][b][q] = 0.f;

    auto load_stage = [&](int kt, int buf) {
        uint32_t base = sbase + (uint32_t)buf * 49152u;
#pragma unroll
        for (int i = 0; i < 2; i++)
            cp16(base + a_off[i], a_src[i] + kt * 64, a_sz[i]);
#pragma unroll
        for (int i = 0; i < 4; i++)
            cp16(base + 16384u + b_off[i], b_src[i] + kt * 64, 16);
    };

    load_stage(0, 0); cp_commit();
    load_stage(1, 1); cp_commit();
    load_stage(2, 2); cp_commit();

    const int KT = INTER / 64;  // 44
    for (int kt = 0; kt < KT; kt++) {
        int buf = kt % 3;
        cp_wait2();
        __syncthreads();

        uint32_t bb = sbase + (uint32_t)buf * 49152u;

#pragma unroll
        for (int s = 0; s < 4; s++) {
            uint32_t xw = (uint32_t)((((2 * s + khalf) ^ lr) << 4));
            uint32_t af[2][4];
#pragma unroll
            for (int mi = 0; mi < 2; mi++)
                ldsm_x4(af[mi], bb + a_row[mi] + xw);

            uint32_t bf[8][2];
#pragma unroll
            for (int pi = 0; pi < 4; pi++) {
                uint32_t t4[4];
                ldsm_x4(t4, bb + 16384u + b_row[pi] + xw);
                bf[2*pi][0] = t4[0]; bf[2*pi+1][0] = t4[1];
                bf[2*pi][1] = t4[2]; bf[2*pi+1][1] = t4[3];
            }
#pragma unroll
            for (int mi = 0; mi < 2; mi++)
#pragma unroll
                for (int ni = 0; ni < 8; ni++)
                    mma_f16(acc[mi][ni], af[mi], bf[ni]);
        }
        __syncthreads();
        if (kt + 3 < KT) load_stage(kt + 3, buf);
        cp_commit();
    }

#pragma unroll
    for (int mi = 0; mi < 2; mi++) {
        int r_lo = wm * 32 + mi * 16 + (lane >> 2);
#pragma unroll
        for (int half = 0; half < 2; half++) {
            int row = r_lo + half * 8;
            if (row >= rows) continue;
            float* orow = g_dout + (size_t)(m0 + row) * HIDDEN;
#pragma unroll
            for (int ni = 0; ni < 8; ni++) {
                int coln = n0 + wn * 64 + ni * 8 + (lane & 3) * 2;
                float2 o;
                o.x = acc[mi][ni][half * 2 + 0];
                o.y = acc[mi][ni][half * 2 + 1];
                *(float2*)&orow[coln] = o;
            }
        }
    }
}

// ---------------- combine ----------------
__global__ void k_combine(float* __restrict__ out) {
    int t = blockIdx.x, j = threadIdx.x;
    int s0 = g_slot0[t], s1 = g_slot1[t];
    float w0 = g_w0[t], w1 = g_w1[t];
    float4 a = ((const float4*)(g_dout + (size_t)s0 * HIDDEN))[j];
    float4 b = ((const float4*)(g_dout + (size_t)s1 * HIDDEN))[j];
    float4 o;
    o.x = w0 * a.x + w1 * b.x;
    o.y = w0 * a.y + w1 * b.y;
    o.z = w0 * a.z + w1 * b.z;
    o.w = w0 * a.w + w1 * b.w;
    ((float4*)(out + (size_t)t * HIDDEN))[j] = o;
}

// ---------------- launch ----------------
extern "C" void kernel_launch(void* const* d_in, const int* in_sizes, int n_in,
                              void* d_out, int out_size) {
    const float* x   = (const float*)d_in[0];
    const float* wg  = (const float*)d_in[1];
    const float* wgp = (const float*)d_in[2];
    const float* wup = (const float*)d_in[3];
    const float* wdp = (const float*)d_in[4];
    float* out = (float*)d_out;

    const int SMEM_DYN = 3 * 49152;  // 147456 B
    cudaFuncSetAttribute(k_gateup, cudaFuncAttributeMaxDynamicSharedMemorySize, SMEM_DYN);
    cudaFuncSetAttribute(k_down,   cudaFuncAttributeMaxDynamicSharedMemorySize, SMEM_DYN);

    k_zero<<<1, 32>>>();
    k_route<<<TOKENS / 8, 256>>>(x, wg);
    k_plan<<<1, 1>>>();
    k_scatter<<<TOKENS / 256, 256>>>();

    long long ncvt = (long long)NX4 + 3LL * NW4;
    k_cvt<<<(unsigned)((ncvt + 255) / 256), 256>>>(x, wgp, wup, wdp);

    k_gateup<<<dim3(INTER / 128, 136), 512, SMEM_DYN>>>();
    k_down  <<<dim3(HIDDEN / 256, 136), 512, SMEM_DYN>>>();
    k_combine<<<TOKENS, 256>>>(out);
}

// round 7
// speedup vs baseline: 2.3076x; 1.0290x over previous
#include <cuda_runtime.h>
#include <cuda_fp16.h>
#include <cstdint>

#define TOKENS 8192
#define HIDDEN 1024
#define INTER  2816
#define NEXP   8
#define NSLOTS (2*TOKENS)
#define MAX_TILES 160
#define BM 128

// ---------------- device scratch ----------------
__device__ int   g_cnt[NEXP];
__device__ int   g_cur[NEXP];
__device__ int   g_off[NEXP + 1];
__device__ int   g_e0[TOKENS];
__device__ int   g_e1[TOKENS];
__device__ float g_w0[TOKENS];
__device__ float g_w1[TOKENS];
__device__ int   g_row_token[NSLOTS];
__device__ int   g_slot0[TOKENS];
__device__ int   g_slot1[TOKENS];
__device__ int   g_tile_e[MAX_TILES];
__device__ int   g_tile_m0[MAX_TILES];
__device__ int   g_tile_rows[MAX_TILES];
__device__ int   g_ntiles;

__device__ __half g_xh  [(size_t)TOKENS * HIDDEN];
__device__ __half g_wgph[(size_t)NEXP * INTER * HIDDEN];
__device__ __half g_wuph[(size_t)NEXP * INTER * HIDDEN];
__device__ __half g_wdph[(size_t)NEXP * HIDDEN * INTER];
__device__ __half g_act [(size_t)NSLOTS * INTER];
__device__ float  g_dout[(size_t)NSLOTS * HIDDEN];

// ---------------- helpers ----------------
__device__ __forceinline__ uint32_t smem_u32(const void* p) {
    uint32_t a;
    asm("{ .reg .u64 t; cvta.to.shared.u64 t, %1; cvt.u32.u64 %0, t; }" : "=r"(a) : "l"(p));
    return a;
}
__device__ __forceinline__ void cp16(uint32_t dst, const void* src, int src_sz) {
    asm volatile("cp.async.cg.shared.global [%0], [%1], 16, %2;\n"
                 :: "r"(dst), "l"(src), "r"(src_sz) : "memory");
}
__device__ __forceinline__ void cp_commit() {
    asm volatile("cp.async.commit_group;\n" ::: "memory");
}
__device__ __forceinline__ void cp_wait2() {
    asm volatile("cp.async.wait_group 2;\n" ::: "memory");
}
__device__ __forceinline__ void mma_f16(float* c, const uint32_t* a, const uint32_t* b) {
    asm volatile(
        "mma.sync.aligned.m16n8k16.row.col.f32.f16.f16.f32 "
        "{%0,%1,%2,%3},{%4,%5,%6,%7},{%8,%9},{%0,%1,%2,%3};"
        : "+f"(c[0]), "+f"(c[1]), "+f"(c[2]), "+f"(c[3])
        : "r"(a[0]), "r"(a[1]), "r"(a[2]), "r"(a[3]), "r"(b[0]), "r"(b[1]));
}
__device__ __forceinline__ void ldsm_x4(uint32_t* r, uint32_t addr) {
    asm volatile("ldmatrix.sync.aligned.m8n8.x4.shared.b16 {%0,%1,%2,%3}, [%4];"
                 : "=r"(r[0]), "=r"(r[1]), "=r"(r[2]), "=r"(r[3]) : "r"(addr));
}

// ---------------- routing ----------------
__global__ void k_zero() { if (threadIdx.x < NEXP) g_cnt[threadIdx.x] = 0; }

__global__ void k_route(const float* __restrict__ x, const float* __restrict__ wg) {
    __shared__ float s_wg[NEXP * HIDDEN];
    int tid = threadIdx.x;
    for (int i = tid * 4; i < NEXP * HIDDEN; i += blockDim.x * 4)
        *(float4*)&s_wg[i] = *(const float4*)&wg[i];
    __syncthreads();
    int warp = tid >> 5, lane = tid & 31;
    int t = blockIdx.x * 8 + warp;
    float p[NEXP];
#pragma unroll
    for (int e = 0; e < NEXP; e++) p[e] = 0.f;
    const float* xr = x + (size_t)t * HIDDEN;
    for (int k = lane; k < HIDDEN; k += 32) {
        float xv = xr[k];
#pragma unroll
        for (int e = 0; e < NEXP; e++) p[e] += xv * s_wg[e * HIDDEN + k];
    }
#pragma unroll
    for (int e = 0; e < NEXP; e++)
#pragma unroll
        for (int o = 16; o; o >>= 1) p[e] += __shfl_xor_sync(0xffffffffu, p[e], o);
    if (lane == 0) {
        int e0 = 0;
#pragma unroll
        for (int e = 1; e < NEXP; e++) if (p[e] > p[e0]) e0 = e;
        int e1 = -1; float v1 = -1e30f;
#pragma unroll
        for (int e = 0; e < NEXP; e++) {
            if (e == e0) continue;
            if (e1 < 0 || p[e] > v1) { e1 = e; v1 = p[e]; }
        }
        float b = __expf(v1 - p[e0]);
        float inv = 1.f / (1.f + b);
        g_e0[t] = e0; g_e1[t] = e1;
        g_w0[t] = inv; g_w1[t] = b * inv;
        atomicAdd(&g_cnt[e0], 1);
        atomicAdd(&g_cnt[e1], 1);
    }
}

__global__ void k_plan() {
    if (threadIdx.x == 0) {
        int off = 0, nt = 0;
        for (int e = 0; e < NEXP; e++) {
            g_off[e] = off;
            int c = g_cnt[e];
            int m0 = 0;
            while (m0 < c) {
                g_tile_e[nt] = e;
                g_tile_m0[nt] = off + m0;
                g_tile_rows[nt] = min(BM, c - m0);
                m0 += BM; nt++;
            }
            off += c;
            g_cur[e] = 0;
        }
        g_off[NEXP] = off;
        g_ntiles = nt;
    }
}

__global__ void k_scatter() {
    int t = blockIdx.x * blockDim.x + threadIdx.x;
    if (t >= TOKENS) return;
    int e0 = g_e0[t], e1 = g_e1[t];
    int i0 = g_off[e0] + atomicAdd(&g_cur[e0], 1);
    g_row_token[i0] = t; g_slot0[t] = i0;
    int i1 = g_off[e1] + atomicAdd(&g_cur[e1], 1);
    g_row_token[i1] = t; g_slot1[t] = i1;
}

// ---------------- merged fp32 -> fp16 conversion ----------------
#define NX4 ((TOKENS * HIDDEN) / 4)
#define NW4 ((NEXP * INTER * HIDDEN) / 4)
__global__ void k_cvt(const float* __restrict__ x,
                      const float* __restrict__ wgp,
                      const float* __restrict__ wup,
                      const float* __restrict__ wdp) {
    long long i = (long long)blockIdx.x * blockDim.x + threadIdx.x;
    const float* src; __half* dst; long long j;
    if (i < NX4)                { src = x;   dst = g_xh;   j = i; }
    else if (i < NX4 + NW4)     { src = wgp; dst = g_wgph; j = i - NX4; }
    else if (i < NX4 + 2*NW4)   { src = wup; dst = g_wuph; j = i - NX4 - NW4; }
    else if (i < NX4 + 3*NW4)   { src = wdp; dst = g_wdph; j = i - NX4 - 2*NW4; }
    else return;
    float4 v = ((const float4*)src)[j];
    __half2 h01 = __floats2half2_rn(v.x, v.y);
    __half2 h23 = __floats2half2_rn(v.z, v.w);
    uint2 o;
    o.x = *(uint32_t*)&h01;
    o.y = *(uint32_t*)&h23;
    ((uint2*)dst)[j] = o;
}

// ---------------- K4: gate+up GEMM + SwiGLU ----------------
// CTA 128(tok) x 128(inter), 512 thr (16 warps 4m x 4n, warp tile 32x32/matrix),
// BK=64, 4-stage cp.async ring, one barrier per k-tile, loads-before-compute.
__global__ void __launch_bounds__(512, 1)
k_gateup() {
    int bt = blockIdx.y;
    if (bt >= g_ntiles) return;
    int e = g_tile_e[bt], m0 = g_tile_m0[bt], rows = g_tile_rows[bt];
    int n0 = blockIdx.x * 128;

    extern __shared__ uint32_t dsm[];
    uint32_t sbase = smem_u32(dsm);

    int tid = threadIdx.x, warp = tid >> 5, lane = tid & 31;
    int wm = warp & 3, wn = warp >> 2;

    const __half* wg_e = g_wgph + (size_t)e * INTER * HIDDEN;
    const __half* wu_e = g_wuph + (size_t)e * INTER * HIDDEN;

    const __half* a_src[2]; int a_sz[2];
    const __half* bg_src[2]; const __half* bu_src[2];
    uint32_t soff[2];
#pragma unroll
    for (int i = 0; i < 2; i++) {
        int c = tid + 512 * i;
        int r = c >> 3, c8 = c & 7;
        bool v = r < rows;
        int tok = v ? g_row_token[m0 + r] : 0;
        a_src[i] = g_xh + (size_t)tok * HIDDEN + c8 * 8;
        a_sz[i] = v ? 16 : 0;
        bg_src[i] = wg_e + (size_t)(n0 + r) * HIDDEN + c8 * 8;
        bu_src[i] = wu_e + (size_t)(n0 + r) * HIDDEN + c8 * 8;
        soff[i] = (uint32_t)(r * 128 + ((c8 ^ (r & 7)) << 4));
    }

    int lr = lane & 7, grp = lane >> 3;
    int rsel = (grp & 1) << 3;
    int khalf = grp >> 1;
    uint32_t a_row[2], b_row[2];
#pragma unroll
    for (int mi = 0; mi < 2; mi++)
        a_row[mi] = (uint32_t)((wm * 32 + mi * 16 + rsel + lr) * 128);
#pragma unroll
    for (int pi = 0; pi < 2; pi++)
        b_row[pi] = (uint32_t)((wn * 32 + pi * 16 + rsel + lr) * 128);

    float accG[2][4][4], accU[2][4][4];
#pragma unroll
    for (int a = 0; a < 2; a++)
#pragma unroll
        for (int b = 0; b < 4; b++)
#pragma unroll
            for (int q = 0; q < 4; q++) { accG[a][b][q] = 0.f; accU[a][b][q] = 0.f; }

    auto load_stage = [&](int kt, int buf) {
        uint32_t base = sbase + (uint32_t)buf * 49152u;
#pragma unroll
        for (int i = 0; i < 2; i++) {
            cp16(base + soff[i],          a_src[i]  + kt * 64, a_sz[i]);
            cp16(base + 16384u + soff[i], bg_src[i] + kt * 64, 16);
            cp16(base + 32768u + soff[i], bu_src[i] + kt * 64, 16);
        }
    };

    load_stage(0, 0); cp_commit();
    load_stage(1, 1); cp_commit();
    load_stage(2, 2); cp_commit();

    const int KT = HIDDEN / 64;  // 16
    for (int kt0 = 0; kt0 < KT; kt0 += 4) {
#pragma unroll
        for (int u = 0; u < 4; u++) {
            int kt = kt0 + u;
            int buf = kt & 3;
            cp_wait2();
            __syncthreads();
            // issue next loads FIRST: buffer (kt+3)&3 == (kt-1)&3 was fully
            // consumed before the barrier all warps just passed.
            if (kt + 3 < KT) load_stage(kt + 3, (kt + 3) & 3);
            cp_commit();

            uint32_t bb = sbase + (uint32_t)buf * 49152u;
#pragma unroll
            for (int s = 0; s < 4; s++) {
                uint32_t xw = (uint32_t)((((2 * s + khalf) ^ lr) << 4));
                uint32_t af[2][4];
#pragma unroll
                for (int mi = 0; mi < 2; mi++)
                    ldsm_x4(af[mi], bb + a_row[mi] + xw);

                uint32_t bgf[4][2], buf16[4][2];
#pragma unroll
                for (int pi = 0; pi < 2; pi++) {
                    uint32_t t4[4];
                    ldsm_x4(t4, bb + 16384u + b_row[pi] + xw);
                    bgf[2*pi][0] = t4[0]; bgf[2*pi+1][0] = t4[1];
                    bgf[2*pi][1] = t4[2]; bgf[2*pi+1][1] = t4[3];
                    ldsm_x4(t4, bb + 32768u + b_row[pi] + xw);
                    buf16[2*pi][0] = t4[0]; buf16[2*pi+1][0] = t4[1];
                    buf16[2*pi][1] = t4[2]; buf16[2*pi+1][1] = t4[3];
                }
#pragma unroll
                for (int mi = 0; mi < 2; mi++)
#pragma unroll
                    for (int ni = 0; ni < 4; ni++) {
                        mma_f16(accG[mi][ni], af[mi], bgf[ni]);
                        mma_f16(accU[mi][ni], af[mi], buf16[ni]);
                    }
            }
        }
    }

    // epilogue: act = fp16(silu(g) * u)
#pragma unroll
    for (int mi = 0; mi < 2; mi++) {
        int r_lo = wm * 32 + mi * 16 + (lane >> 2);
#pragma unroll
        for (int half = 0; half < 2; half++) {
            int row = r_lo + half * 8;
            if (row >= rows) continue;
            __half* arow = g_act + (size_t)(m0 + row) * INTER;
#pragma unroll
            for (int ni = 0; ni < 4; ni++) {
                int coln = n0 + wn * 32 + ni * 8 + (lane & 3) * 2;
                float g0 = accG[mi][ni][half * 2 + 0];
                float g1 = accG[mi][ni][half * 2 + 1];
                float u0 = accU[mi][ni][half * 2 + 0];
                float u1 = accU[mi][ni][half * 2 + 1];
                float s0 = g0 / (1.f + __expf(-g0)) * u0;
                float s1 = g1 / (1.f + __expf(-g1)) * u1;
                __half2 h = __floats2half2_rn(s0, s1);
                *(__half2*)&arow[coln] = h;
            }
        }
    }
}

// ---------------- K5: down GEMM ----------------
// CTA 128(slots) x 256(hidden), 512 thr (16 warps 4m x 4n, warp tile 32x64),
// BK=64, 4-stage ring, one barrier per k-tile.
__global__ void __launch_bounds__(512, 1)
k_down() {
    int bt = blockIdx.y;
    if (bt >= g_ntiles) return;
    int e = g_tile_e[bt], m0 = g_tile_m0[bt], rows = g_tile_rows[bt];
    int n0 = blockIdx.x * 256;

    extern __shared__ uint32_t dsm[];
    uint32_t sbase = smem_u32(dsm);

    int tid = threadIdx.x, warp = tid >> 5, lane = tid & 31;
    int wm = warp & 3, wn = warp >> 2;

    const __half* wd_e = g_wdph + (size_t)e * HIDDEN * INTER;

    const __half* a_src[2]; int a_sz[2]; uint32_t a_off[2];
    const __half* b_src[4]; uint32_t b_off[4];
#pragma unroll
    for (int i = 0; i < 2; i++) {
        int c = tid + 512 * i;
        int r = c >> 3, c8 = c & 7;
        bool v = r < rows;
        a_src[i] = g_act + (size_t)(m0 + (v ? r : 0)) * INTER + c8 * 8;
        a_sz[i] = v ? 16 : 0;
        a_off[i] = (uint32_t)(r * 128 + ((c8 ^ (r & 7)) << 4));
    }
#pragma unroll
    for (int i = 0; i < 4; i++) {
        int c = tid + 512 * i;
        int r = c >> 3, c8 = c & 7;
        b_src[i] = wd_e + (size_t)(n0 + r) * INTER + c8 * 8;
        b_off[i] = (uint32_t)(r * 128 + ((c8 ^ (r & 7)) << 4));
    }

    int lr = lane & 7, grp = lane >> 3;
    int rsel = (grp & 1) << 3;
    int khalf = grp >> 1;
    uint32_t a_row[2], b_row[4];
#pragma unroll
    for (int mi = 0; mi < 2; mi++)
        a_row[mi] = (uint32_t)((wm * 32 + mi * 16 + rsel + lr) * 128);
#pragma unroll
    for (int pi = 0; pi < 4; pi++)
        b_row[pi] = (uint32_t)((wn * 64 + pi * 16 + rsel + lr) * 128);

    float acc[2][8][4];
#pragma unroll
    for (int a = 0; a < 2; a++)
#pragma unroll
        for (int b = 0; b < 8; b++)
#pragma unroll
            for (int q = 0; q < 4; q++) acc[a][b][q] = 0.f;

    auto load_stage = [&](int kt, int buf) {
        uint32_t base = sbase + (uint32_t)buf * 49152u;
#pragma unroll
        for (int i = 0; i < 2; i++)
            cp16(base + a_off[i], a_src[i] + kt * 64, a_sz[i]);
#pragma unroll
        for (int i = 0; i < 4; i++)
            cp16(base + 16384u + b_off[i], b_src[i] + kt * 64, 16);
    };

    load_stage(0, 0); cp_commit();
    load_stage(1, 1); cp_commit();
    load_stage(2, 2); cp_commit();

    const int KT = INTER / 64;  // 44
    for (int kt0 = 0; kt0 < KT; kt0 += 4) {
#pragma unroll
        for (int u = 0; u < 4; u++) {
            int kt = kt0 + u;
            int buf = kt & 3;
            cp_wait2();
            __syncthreads();
            if (kt + 3 < KT) load_stage(kt + 3, (kt + 3) & 3);
            cp_commit();

            uint32_t bb = sbase + (uint32_t)buf * 49152u;
#pragma unroll
            for (int s = 0; s < 4; s++) {
                uint32_t xw = (uint32_t)((((2 * s + khalf) ^ lr) << 4));
                uint32_t af[2][4];
#pragma unroll
                for (int mi = 0; mi < 2; mi++)
                    ldsm_x4(af[mi], bb + a_row[mi] + xw);

                uint32_t bf[8][2];
#pragma unroll
                for (int pi = 0; pi < 4; pi++) {
                    uint32_t t4[4];
                    ldsm_x4(t4, bb + 16384u + b_row[pi] + xw);
                    bf[2*pi][0] = t4[0]; bf[2*pi+1][0] = t4[1];
                    bf[2*pi][1] = t4[2]; bf[2*pi+1][1] = t4[3];
                }
#pragma unroll
                for (int mi = 0; mi < 2; mi++)
#pragma unroll
                    for (int ni = 0; ni < 8; ni++)
                        mma_f16(acc[mi][ni], af[mi], bf[ni]);
            }
        }
    }

#pragma unroll
    for (int mi = 0; mi < 2; mi++) {
        int r_lo = wm * 32 + mi * 16 + (lane >> 2);
#pragma unroll
        for (int half = 0; half < 2; half++) {
            int row = r_lo + half * 8;
            if (row >= rows) continue;
            float* orow = g_dout + (size_t)(m0 + row) * HIDDEN;
#pragma unroll
            for (int ni = 0; ni < 8; ni++) {
                int coln = n0 + wn * 64 + ni * 8 + (lane & 3) * 2;
                float2 o;
                o.x = acc[mi][ni][half * 2 + 0];
                o.y = acc[mi][ni][half * 2 + 1];
                *(float2*)&orow[coln] = o;
            }
        }
    }
}

// ---------------- combine ----------------
__global__ void k_combine(float* __restrict__ out) {
    int t = blockIdx.x, j = threadIdx.x;
    int s0 = g_slot0[t], s1 = g_slot1[t];
    float w0 = g_w0[t], w1 = g_w1[t];
    float4 a = ((const float4*)(g_dout + (size_t)s0 * HIDDEN))[j];
    float4 b = ((const float4*)(g_dout + (size_t)s1 * HIDDEN))[j];
    float4 o;
    o.x = w0 * a.x + w1 * b.x;
    o.y = w0 * a.y + w1 * b.y;
    o.z = w0 * a.z + w1 * b.z;
    o.w = w0 * a.w + w1 * b.w;
    ((float4*)(out + (size_t)t * HIDDEN))[j] = o;
}

// ---------------- launch ----------------
extern "C" void kernel_launch(void* const* d_in, const int* in_sizes, int n_in,
                              void* d_out, int out_size) {
    const float* x   = (const float*)d_in[0];
    const float* wg  = (const float*)d_in[1];
    const float* wgp = (const float*)d_in[2];
    const float* wup = (const float*)d_in[3];
    const float* wdp = (const float*)d_in[4];
    float* out = (float*)d_out;

    const int SMEM_DYN = 4 * 49152;  // 196608 B
    cudaFuncSetAttribute(k_gateup, cudaFuncAttributeMaxDynamicSharedMemorySize, SMEM_DYN);
    cudaFuncSetAttribute(k_down,   cudaFuncAttributeMaxDynamicSharedMemorySize, SMEM_DYN);

    k_zero<<<1, 32>>>();
    k_route<<<TOKENS / 8, 256>>>(x, wg);
    k_plan<<<1, 1>>>();
    k_scatter<<<TOKENS / 256, 256>>>();

    long long ncvt = (long long)NX4 + 3LL * NW4;
    k_cvt<<<(unsigned)((ncvt + 255) / 256), 256>>>(x, wgp, wup, wdp);

    k_gateup<<<dim3(INTER / 128, 136), 512, SMEM_DYN>>>();
    k_down  <<<dim3(HIDDEN / 256, 136), 512, SMEM_DYN>>>();
    k_combine<<<TOKENS, 256>>>(out);
}

// round 8
// speedup vs baseline: 2.4588x; 1.0655x over previous
#include <cuda_runtime.h>
#include <cuda_fp16.h>
#include <cstdint>

#define TOKENS 8192
#define HIDDEN 1024
#define INTER  2816
#define NEXP   8
#define NSLOTS (2*TOKENS)
#define MAX_TILES 160
#define BM 128

// ---------------- device scratch ----------------
__device__ int   g_cnt[NEXP];
__device__ int   g_cur[NEXP];
__device__ int   g_off[NEXP + 1];
__device__ int   g_e0[TOKENS];
__device__ int   g_e1[TOKENS];
__device__ float g_w0[TOKENS];
__device__ float g_w1[TOKENS];
__device__ int   g_row_token[NSLOTS];
__device__ float g_row_w[NSLOTS];
__device__ int   g_tile_e[MAX_TILES];
__device__ int   g_tile_m0[MAX_TILES];
__device__ int   g_tile_rows[MAX_TILES];
__device__ int   g_ntiles;

__device__ __half g_xh  [(size_t)TOKENS * HIDDEN];
__device__ __half g_wgph[(size_t)NEXP * INTER * HIDDEN];
__device__ __half g_wuph[(size_t)NEXP * INTER * HIDDEN];
__device__ __half g_wdph[(size_t)NEXP * HIDDEN * INTER];
__device__ __half g_act [(size_t)NSLOTS * INTER];

// ---------------- helpers ----------------
__device__ __forceinline__ uint32_t smem_u32(const void* p) {
    uint32_t a;
    asm("{ .reg .u64 t; cvta.to.shared.u64 t, %1; cvt.u32.u64 %0, t; }" : "=r"(a) : "l"(p));
    return a;
}
__device__ __forceinline__ void cp16(uint32_t dst, const void* src, int src_sz) {
    asm volatile("cp.async.cg.shared.global [%0], [%1], 16, %2;\n"
                 :: "r"(dst), "l"(src), "r"(src_sz) : "memory");
}
__device__ __forceinline__ void cp_commit() {
    asm volatile("cp.async.commit_group;\n" ::: "memory");
}
__device__ __forceinline__ void cp_wait2() {
    asm volatile("cp.async.wait_group 2;\n" ::: "memory");
}
__device__ __forceinline__ void mma_f16(float* c, const uint32_t* a, const uint32_t* b) {
    asm volatile(
        "mma.sync.aligned.m16n8k16.row.col.f32.f16.f16.f32 "
        "{%0,%1,%2,%3},{%4,%5,%6,%7},{%8,%9},{%0,%1,%2,%3};"
        : "+f"(c[0]), "+f"(c[1]), "+f"(c[2]), "+f"(c[3])
        : "r"(a[0]), "r"(a[1]), "r"(a[2]), "r"(a[3]), "r"(b[0]), "r"(b[1]));
}
__device__ __forceinline__ void ldsm_x4(uint32_t* r, uint32_t addr) {
    asm volatile("ldmatrix.sync.aligned.m8n8.x4.shared.b16 {%0,%1,%2,%3}, [%4];"
                 : "=r"(r[0]), "=r"(r[1]), "=r"(r[2]), "=r"(r[3]) : "r"(addr));
}

// ---------------- routing ----------------
__global__ void k_zero() { if (threadIdx.x < NEXP) g_cnt[threadIdx.x] = 0; }

__global__ void k_route(const float* __restrict__ x, const float* __restrict__ wg) {
    __shared__ float s_wg[NEXP * HIDDEN];
    int tid = threadIdx.x;
    for (int i = tid * 4; i < NEXP * HIDDEN; i += blockDim.x * 4)
        *(float4*)&s_wg[i] = *(const float4*)&wg[i];
    __syncthreads();
    int warp = tid >> 5, lane = tid & 31;
    int t = blockIdx.x * 8 + warp;
    float p[NEXP];
#pragma unroll
    for (int e = 0; e < NEXP; e++) p[e] = 0.f;
    const float* xr = x + (size_t)t * HIDDEN;
    for (int k = lane; k < HIDDEN; k += 32) {
        float xv = xr[k];
#pragma unroll
        for (int e = 0; e < NEXP; e++) p[e] += xv * s_wg[e * HIDDEN + k];
    }
#pragma unroll
    for (int e = 0; e < NEXP; e++)
#pragma unroll
        for (int o = 16; o; o >>= 1) p[e] += __shfl_xor_sync(0xffffffffu, p[e], o);
    if (lane == 0) {
        int e0 = 0;
#pragma unroll
        for (int e = 1; e < NEXP; e++) if (p[e] > p[e0]) e0 = e;
        int e1 = -1; float v1 = -1e30f;
#pragma unroll
        for (int e = 0; e < NEXP; e++) {
            if (e == e0) continue;
            if (e1 < 0 || p[e] > v1) { e1 = e; v1 = p[e]; }
        }
        float b = __expf(v1 - p[e0]);
        float inv = 1.f / (1.f + b);
        g_e0[t] = e0; g_e1[t] = e1;
        g_w0[t] = inv; g_w1[t] = b * inv;
        atomicAdd(&g_cnt[e0], 1);
        atomicAdd(&g_cnt[e1], 1);
    }
}

__global__ void k_plan() {
    if (threadIdx.x == 0) {
        int off = 0, nt = 0;
        for (int e = 0; e < NEXP; e++) {
            g_off[e] = off;
            int c = g_cnt[e];
            int m0 = 0;
            while (m0 < c) {
                g_tile_e[nt] = e;
                g_tile_m0[nt] = off + m0;
                g_tile_rows[nt] = min(BM, c - m0);
                m0 += BM; nt++;
            }
            off += c;
            g_cur[e] = 0;
        }
        g_off[NEXP] = off;
        g_ntiles = nt;
    }
}

__global__ void k_scatter() {
    int t = blockIdx.x * blockDim.x + threadIdx.x;
    if (t >= TOKENS) return;
    int e0 = g_e0[t], e1 = g_e1[t];
    int i0 = g_off[e0] + atomicAdd(&g_cur[e0], 1);
    g_row_token[i0] = t; g_row_w[i0] = g_w0[t];
    int i1 = g_off[e1] + atomicAdd(&g_cur[e1], 1);
    g_row_token[i1] = t; g_row_w[i1] = g_w1[t];
}

// ---------------- merged fp32 -> fp16 conversion ----------------
#define NX4 ((TOKENS * HIDDEN) / 4)
#define NW4 ((NEXP * INTER * HIDDEN) / 4)
__global__ void k_cvt(const float* __restrict__ x,
                      const float* __restrict__ wgp,
                      const float* __restrict__ wup,
                      const float* __restrict__ wdp) {
    long long i = (long long)blockIdx.x * blockDim.x + threadIdx.x;
    const float* src; __half* dst; long long j;
    if (i < NX4)                { src = x;   dst = g_xh;   j = i; }
    else if (i < NX4 + NW4)     { src = wgp; dst = g_wgph; j = i - NX4; }
    else if (i < NX4 + 2*NW4)   { src = wup; dst = g_wuph; j = i - NX4 - NW4; }
    else if (i < NX4 + 3*NW4)   { src = wdp; dst = g_wdph; j = i - NX4 - 2*NW4; }
    else return;
    float4 v = ((const float4*)src)[j];
    __half2 h01 = __floats2half2_rn(v.x, v.y);
    __half2 h23 = __floats2half2_rn(v.z, v.w);
    uint2 o;
    o.x = *(uint32_t*)&h01;
    o.y = *(uint32_t*)&h23;
    ((uint2*)dst)[j] = o;
}

// ---------------- K4: gate+up GEMM + SwiGLU ----------------
// CTA 128(tok) x 64(inter) per matrix; 256 thr, 8 warps 4m x 2n,
// warp tile 32x32 per matrix; BK=64; 3-stage ring (32KB/stage); 2 CTAs/SM.
__global__ void __launch_bounds__(256, 2)
k_gateup() {
    int bt = blockIdx.y;
    if (bt >= g_ntiles) return;
    int e = g_tile_e[bt], m0 = g_tile_m0[bt], rows = g_tile_rows[bt];
    int n0 = blockIdx.x * 64;

    extern __shared__ uint32_t dsm[];
    uint32_t sbase = smem_u32(dsm);

    int tid = threadIdx.x, warp = tid >> 5, lane = tid & 31;
    int wm = warp & 3, wn = warp >> 2;

    const __half* wg_e = g_wgph + (size_t)e * INTER * HIDDEN;
    const __half* wu_e = g_wuph + (size_t)e * INTER * HIDDEN;

    // A: 128 rows x 8 chunks = 4 chunks/thread; G/U: 64 rows x 8 = 2 chunks/thread
    const __half* a_src[4]; int a_sz[4]; uint32_t a_off[4];
#pragma unroll
    for (int i = 0; i < 4; i++) {
        int c = tid + 256 * i;
        int r = c >> 3, c8 = c & 7;
        bool v = r < rows;
        int tok = v ? g_row_token[m0 + r] : 0;
        a_src[i] = g_xh + (size_t)tok * HIDDEN + c8 * 8;
        a_sz[i] = v ? 16 : 0;
        a_off[i] = (uint32_t)(r * 128 + ((c8 ^ (r & 7)) << 4));
    }
    const __half* bg_src[2]; const __half* bu_src[2]; uint32_t b_off[2];
#pragma unroll
    for (int i = 0; i < 2; i++) {
        int c = tid + 256 * i;
        int r = c >> 3, c8 = c & 7;
        bg_src[i] = wg_e + (size_t)(n0 + r) * HIDDEN + c8 * 8;
        bu_src[i] = wu_e + (size_t)(n0 + r) * HIDDEN + c8 * 8;
        b_off[i] = (uint32_t)(r * 128 + ((c8 ^ (r & 7)) << 4));
    }

    int lr = lane & 7, grp = lane >> 3;
    int rsel = (grp & 1) << 3;
    int khalf = grp >> 1;
    uint32_t a_row[2], b_row[2];
#pragma unroll
    for (int mi = 0; mi < 2; mi++)
        a_row[mi] = (uint32_t)((wm * 32 + mi * 16 + rsel + lr) * 128);
#pragma unroll
    for (int pi = 0; pi < 2; pi++)
        b_row[pi] = (uint32_t)((wn * 32 + pi * 16 + rsel + lr) * 128);

    float accG[2][4][4], accU[2][4][4];
#pragma unroll
    for (int a = 0; a < 2; a++)
#pragma unroll
        for (int b = 0; b < 4; b++)
#pragma unroll
            for (int q = 0; q < 4; q++) { accG[a][b][q] = 0.f; accU[a][b][q] = 0.f; }

    // stage layout: A @0 (16KB) | G @16384 (8KB) | U @24576 (8KB); stride 32768
    auto load_stage = [&](int kt, int buf) {
        uint32_t base = sbase + (uint32_t)buf * 32768u;
#pragma unroll
        for (int i = 0; i < 4; i++)
            cp16(base + a_off[i], a_src[i] + kt * 64, a_sz[i]);
#pragma unroll
        for (int i = 0; i < 2; i++) {
            cp16(base + 16384u + b_off[i], bg_src[i] + kt * 64, 16);
            cp16(base + 24576u + b_off[i], bu_src[i] + kt * 64, 16);
        }
    };

    load_stage(0, 0); cp_commit();
    load_stage(1, 1); cp_commit();
    load_stage(2, 2); cp_commit();

    const int KT = HIDDEN / 64;  // 16
    for (int kt = 0; kt < KT; kt++) {
        int buf = kt % 3;
        cp_wait2();
        __syncthreads();

        uint32_t bb = sbase + (uint32_t)buf * 32768u;
#pragma unroll
        for (int s = 0; s < 4; s++) {
            uint32_t xw = (uint32_t)((((2 * s + khalf) ^ lr) << 4));
            uint32_t af[2][4];
#pragma unroll
            for (int mi = 0; mi < 2; mi++)
                ldsm_x4(af[mi], bb + a_row[mi] + xw);

            uint32_t bgf[4][2], buf16[4][2];
#pragma unroll
            for (int pi = 0; pi < 2; pi++) {
                uint32_t t4[4];
                ldsm_x4(t4, bb + 16384u + b_row[pi] + xw);
                bgf[2*pi][0] = t4[0]; bgf[2*pi+1][0] = t4[1];
                bgf[2*pi][1] = t4[2]; bgf[2*pi+1][1] = t4[3];
                ldsm_x4(t4, bb + 24576u + b_row[pi] + xw);
                buf16[2*pi][0] = t4[0]; buf16[2*pi+1][0] = t4[1];
                buf16[2*pi][1] = t4[2]; buf16[2*pi+1][1] = t4[3];
            }
#pragma unroll
            for (int mi = 0; mi < 2; mi++)
#pragma unroll
                for (int ni = 0; ni < 4; ni++) {
                    mma_f16(accG[mi][ni], af[mi], bgf[ni]);
                    mma_f16(accU[mi][ni], af[mi], buf16[ni]);
                }
        }
        __syncthreads();
        if (kt + 3 < KT) load_stage(kt + 3, buf);
        cp_commit();
    }

    // epilogue: act = fp16(silu(g) * u)
#pragma unroll
    for (int mi = 0; mi < 2; mi++) {
        int r_lo = wm * 32 + mi * 16 + (lane >> 2);
#pragma unroll
        for (int half = 0; half < 2; half++) {
            int row = r_lo + half * 8;
            if (row >= rows) continue;
            __half* arow = g_act + (size_t)(m0 + row) * INTER;
#pragma unroll
            for (int ni = 0; ni < 4; ni++) {
                int coln = n0 + wn * 32 + ni * 8 + (lane & 3) * 2;
                float g0 = accG[mi][ni][half * 2 + 0];
                float g1 = accG[mi][ni][half * 2 + 1];
                float u0 = accU[mi][ni][half * 2 + 0];
                float u1 = accU[mi][ni][half * 2 + 1];
                float s0 = g0 / (1.f + __expf(-g0)) * u0;
                float s1 = g1 / (1.f + __expf(-g1)) * u1;
                __half2 h = __floats2half2_rn(s0, s1);
                *(__half2*)&arow[coln] = h;
            }
        }
    }
}

// ---------------- K5: down GEMM -> weighted atomic combine ----------------
// CTA 128(slots) x 128(hidden); 256 thr, 8 warps 4m x 2n, warp tile 32x64;
// BK=64; 3-stage ring (32KB/stage); 2 CTAs/SM. Epilogue: out += w * acc
// (exactly two commutative fp32 atomic adds per element -> deterministic).
__global__ void __launch_bounds__(256, 2)
k_down(float* __restrict__ out) {
    int bt = blockIdx.y;
    if (bt >= g_ntiles) return;
    int e = g_tile_e[bt], m0 = g_tile_m0[bt], rows = g_tile_rows[bt];
    int n0 = blockIdx.x * 128;

    extern __shared__ uint32_t dsm[];
    uint32_t sbase = smem_u32(dsm);

    int tid = threadIdx.x, warp = tid >> 5, lane = tid & 31;
    int wm = warp & 3, wn = warp >> 2;

    const __half* wd_e = g_wdph + (size_t)e * HIDDEN * INTER;

    const __half* a_src[4]; int a_sz[4]; uint32_t a_off[4];
    const __half* b_src[4]; uint32_t b_off[4];
#pragma unroll
    for (int i = 0; i < 4; i++) {
        int c = tid + 256 * i;
        int r = c >> 3, c8 = c & 7;
        bool v = r < rows;
        a_src[i] = g_act + (size_t)(m0 + (v ? r : 0)) * INTER + c8 * 8;
        a_sz[i] = v ? 16 : 0;
        a_off[i] = (uint32_t)(r * 128 + ((c8 ^ (r & 7)) << 4));
        b_src[i] = wd_e + (size_t)(n0 + r) * INTER + c8 * 8;
        b_off[i] = a_off[i];
    }

    int lr = lane & 7, grp = lane >> 3;
    int rsel = (grp & 1) << 3;
    int khalf = grp >> 1;
    uint32_t a_row[2], b_row[4];
#pragma unroll
    for (int mi = 0; mi < 2; mi++)
        a_row[mi] = (uint32_t)((wm * 32 + mi * 16 + rsel + lr) * 128);
#pragma unroll
    for (int pi = 0; pi < 4; pi++)
        b_row[pi] = (uint32_t)((wn * 64 + pi * 16 + rsel + lr) * 128);

    float acc[2][8][4];
#pragma unroll
    for (int a = 0; a < 2; a++)
#pragma unroll
        for (int b = 0; b < 8; b++)
#pragma unroll
            for (int q = 0; q < 4; q++) acc[a][b][q] = 0.f;

    // stage layout: A @0 (16KB) | B @16384 (16KB); stride 32768
    auto load_stage = [&](int kt, int buf) {
        uint32_t base = sbase + (uint32_t)buf * 32768u;
#pragma unroll
        for (int i = 0; i < 4; i++) {
            cp16(base + a_off[i],          a_src[i] + kt * 64, a_sz[i]);
            cp16(base + 16384u + b_off[i], b_src[i] + kt * 64, 16);
        }
    };

    load_stage(0, 0); cp_commit();
    load_stage(1, 1); cp_commit();
    load_stage(2, 2); cp_commit();

    const int KT = INTER / 64;  // 44
    for (int kt = 0; kt < KT; kt++) {
        int buf = kt % 3;
        cp_wait2();
        __syncthreads();

        uint32_t bb = sbase + (uint32_t)buf * 32768u;
#pragma unroll
        for (int s = 0; s < 4; s++) {
            uint32_t xw = (uint32_t)((((2 * s + khalf) ^ lr) << 4));
            uint32_t af[2][4];
#pragma unroll
            for (int mi = 0; mi < 2; mi++)
                ldsm_x4(af[mi], bb + a_row[mi] + xw);

            uint32_t bf[8][2];
#pragma unroll
            for (int pi = 0; pi < 4; pi++) {
                uint32_t t4[4];
                ldsm_x4(t4, bb + 16384u + b_row[pi] + xw);
                bf[2*pi][0] = t4[0]; bf[2*pi+1][0] = t4[1];
                bf[2*pi][1] = t4[2]; bf[2*pi+1][1] = t4[3];
            }
#pragma unroll
            for (int mi = 0; mi < 2; mi++)
#pragma unroll
                for (int ni = 0; ni < 8; ni++)
                    mma_f16(acc[mi][ni], af[mi], bf[ni]);
        }
        __syncthreads();
        if (kt + 3 < KT) load_stage(kt + 3, buf);
        cp_commit();
    }

    // epilogue: weighted atomic scatter-add into out
#pragma unroll
    for (int mi = 0; mi < 2; mi++) {
        int r_lo = wm * 32 + mi * 16 + (lane >> 2);
#pragma unroll
        for (int half = 0; half < 2; half++) {
            int row = r_lo + half * 8;
            if (row >= rows) continue;
            int tok = g_row_token[m0 + row];
            float w = g_row_w[m0 + row];
            float* orow = out + (size_t)tok * HIDDEN;
#pragma unroll
            for (int ni = 0; ni < 8; ni++) {
                int coln = n0 + wn * 64 + ni * 8 + (lane & 3) * 2;
                atomicAdd(&orow[coln],     w * acc[mi][ni][half * 2 + 0]);
                atomicAdd(&orow[coln + 1], w * acc[mi][ni][half * 2 + 1]);
            }
        }
    }
}

// ---------------- launch ----------------
extern "C" void kernel_launch(void* const* d_in, const int* in_sizes, int n_in,
                              void* d_out, int out_size) {
    const float* x   = (const float*)d_in[0];
    const float* wg  = (const float*)d_in[1];
    const float* wgp = (const float*)d_in[2];
    const float* wup = (const float*)d_in[3];
    const float* wdp = (const float*)d_in[4];
    float* out = (float*)d_out;

    const int SMEM_DYN = 3 * 32768;  // 98304 B per CTA, 2 CTAs/SM
    cudaFuncSetAttribute(k_gateup, cudaFuncAttributeMaxDynamicSharedMemorySize, SMEM_DYN);
    cudaFuncSetAttribute(k_down,   cudaFuncAttributeMaxDynamicSharedMemorySize, SMEM_DYN);

    k_zero<<<1, 32>>>();
    k_route<<<TOKENS / 8, 256>>>(x, wg);
    k_plan<<<1, 1>>>();
    k_scatter<<<TOKENS / 256, 256>>>();

    long long ncvt = (long long)NX4 + 3LL * NW4;
    k_cvt<<<(unsigned)((ncvt + 255) / 256), 256>>>(x, wgp, wup, wdp);

    cudaMemsetAsync(d_out, 0, (size_t)TOKENS * HIDDEN * sizeof(float));

    k_gateup<<<dim3(INTER / 64, 136), 256, SMEM_DYN>>>();
    k_down  <<<dim3(HIDDEN / 128, 136), 256, SMEM_DYN>>>(out);
}